// round 10
// baseline (speedup 1.0000x reference)
#include <cuda_runtime.h>
#include <cuda_fp16.h>
#include <cstdint>

#define BSZ   8192
#define HID   1024
#define KDIM  2048
#define LVL   64
#define NGATE 4096
#define NLEV  128
#define KSPLIT 4

// -------- scratch (static __device__, no allocations) --------
__device__ __half g_A[(size_t)BSZ * KDIM];            // fp16 combined input
__device__ __half g_W[(size_t)(NGATE + NLEV) * KDIM]; // fp16 reordered weights
__device__ float  g_lev[KSPLIT][(size_t)BSZ * NLEV];  // level logit partials (split-K)
__device__ float  g_ih[(size_t)BSZ * LVL];
__device__ float  g_fh[(size_t)BSZ * LVL];

__device__ __forceinline__ float sigmoidf_(float x) { return 1.0f / (1.0f + __expf(-x)); }
__device__ __forceinline__ uint32_t smem_u32(const void* p) {
    return (uint32_t)__cvta_generic_to_shared(p);
}

// -------- prep: fp32 -> fp16 combined activation --------
__global__ void prep_A(const float* __restrict__ inp, const float* __restrict__ hprev) {
    int idx = blockIdx.x * blockDim.x + threadIdx.x;   // float4 index, 512 per row
    int row = idx >> 9;
    int c4  = idx & 511;
    const float* src = (c4 < 256) ? (inp + (size_t)row * 1024 + c4 * 4)
                                  : (hprev + (size_t)row * 1024 + (c4 - 256) * 4);
    float4 v = *reinterpret_cast<const float4*>(src);
    __half2* dst = reinterpret_cast<__half2*>(g_A + (size_t)row * KDIM + c4 * 4);
    dst[0] = __floats2half2_rn(v.x, v.y);
    dst[1] = __floats2half2_rn(v.z, v.w);
}

// -------- prep: fp32 -> fp16 weights, gate-interleaved rows --------
__global__ void prep_W(const float* __restrict__ wl, const float* __restrict__ wv) {
    int idx = blockIdx.x * blockDim.x + threadIdx.x;   // float4 index
    int n  = idx >> 9;
    int c4 = idx & 511;
    const float* src;
    if (n < NGATE) src = wl + (size_t)((n & 3) * 1024 + (n >> 2)) * KDIM + c4 * 4;
    else           src = wv + (size_t)(n - NGATE) * KDIM + c4 * 4;
    float4 v = *reinterpret_cast<const float4*>(src);
    __half2* dst = reinterpret_cast<__half2*>(g_W + (size_t)n * KDIM + c4 * 4);
    dst[0] = __floats2half2_rn(v.x, v.y);
    dst[1] = __floats2half2_rn(v.z, v.w);
}

#define LDS 40   // padded half stride (80B rows) -> conflict-free ldmatrix

// ================= main GEMM: 128x256 tile, 4-stage cp.async, fused epilogue =================
// 8 warps as 2(M) x 4(N); each warp computes 64x64. Dynamic smem:
//   A stages: 4 x (128*40 halves) = 40960 B ; B stages: 4 x (256*40 halves) = 81920 B
__global__ __launch_bounds__(256, 1) void gemm_main(const float* __restrict__ c_prev,
                                                    float* __restrict__ d_out) {
    extern __shared__ __half smem[];
    __half* Abase = smem;                 // 4 stages x 5120 halves
    __half* Bbase = smem + 4 * 5120;      // 4 stages x 10240 halves

    const int tid   = threadIdx.x;
    const int lane  = tid & 31;
    const int wid   = tid >> 5;
    const int warpM = wid >> 2;   // 0..1
    const int warpN = wid & 3;    // 0..3
    const int bm    = blockIdx.y;
    const int bn    = blockIdx.x;

    const __half* Ag = g_A + (size_t)(bm * 128) * KDIM;
    const __half* Bg = g_W + (size_t)(bn * 256) * KDIM;

    float acc[4][8][4];
#pragma unroll
    for (int a = 0; a < 4; a++)
#pragma unroll
        for (int b = 0; b < 8; b++)
#pragma unroll
            for (int c = 0; c < 4; c++) acc[a][b][c] = 0.0f;

    const int KT = KDIM / 32;  // 64

    auto load_stage = [&](int s) {
        int buf = s & 3;
        int k0  = s * 32;
        __half* As = Abase + buf * 5120;
        __half* Bs = Bbase + buf * 10240;
#pragma unroll
        for (int i = 0; i < 2; i++) {          // A: 512 16B chunks
            int lin = tid + i * 256;
            int row = lin >> 2, ch = lin & 3;
            uint32_t dst = smem_u32(As + row * LDS + ch * 8);
            const void* src = Ag + (size_t)row * KDIM + k0 + ch * 8;
            asm volatile("cp.async.cg.shared.global [%0], [%1], 16;" :: "r"(dst), "l"(src));
        }
#pragma unroll
        for (int i = 0; i < 4; i++) {          // B: 1024 16B chunks
            int lin = tid + i * 256;
            int row = lin >> 2, ch = lin & 3;
            uint32_t dst = smem_u32(Bs + row * LDS + ch * 8);
            const void* src = Bg + (size_t)row * KDIM + k0 + ch * 8;
            asm volatile("cp.async.cg.shared.global [%0], [%1], 16;" :: "r"(dst), "l"(src));
        }
    };

#pragma unroll
    for (int s = 0; s < 3; s++) {
        load_stage(s);
        asm volatile("cp.async.commit_group;" ::: "memory");
    }

#pragma unroll 1
    for (int kt = 0; kt < KT; ++kt) {
        if (kt + 3 < KT) load_stage(kt + 3);
        asm volatile("cp.async.commit_group;" ::: "memory");
        asm volatile("cp.async.wait_group 3;" ::: "memory");
        __syncthreads();

        int buf = kt & 3;
        const __half* As = Abase + buf * 5120;
        const __half* Bs = Bbase + buf * 10240;
#pragma unroll
        for (int ks = 0; ks < 2; ++ks) {
            uint32_t afr[4][4];
#pragma unroll
            for (int mi = 0; mi < 4; ++mi) {
                int r  = warpM * 64 + mi * 16 + (lane & 15);
                int ch = ks * 2 + (lane >> 4);
                uint32_t addr = smem_u32(As + r * LDS + ch * 8);
                asm volatile("ldmatrix.sync.aligned.m8n8.x4.shared.b16 {%0,%1,%2,%3}, [%4];"
                             : "=r"(afr[mi][0]), "=r"(afr[mi][1]), "=r"(afr[mi][2]), "=r"(afr[mi][3])
                             : "r"(addr));
            }
            uint32_t bfr[8][2];
#pragma unroll
            for (int np = 0; np < 4; ++np) {
                int r  = warpN * 64 + np * 16 + (lane & 15);
                int ch = ks * 2 + (lane >> 4);
                uint32_t addr = smem_u32(Bs + r * LDS + ch * 8);
                uint32_t r0, r1, r2, r3;
                asm volatile("ldmatrix.sync.aligned.m8n8.x4.shared.b16 {%0,%1,%2,%3}, [%4];"
                             : "=r"(r0), "=r"(r1), "=r"(r2), "=r"(r3)
                             : "r"(addr));
                bfr[np * 2][0] = r0; bfr[np * 2 + 1][0] = r1;
                bfr[np * 2][1] = r2; bfr[np * 2 + 1][1] = r3;
            }
#pragma unroll
            for (int mi = 0; mi < 4; ++mi)
#pragma unroll
                for (int ni = 0; ni < 8; ++ni) {
                    asm volatile(
                        "mma.sync.aligned.m16n8k16.row.col.f32.f16.f16.f32 "
                        "{%0,%1,%2,%3}, {%4,%5,%6,%7}, {%8,%9}, {%0,%1,%2,%3};"
                        : "+f"(acc[mi][ni][0]), "+f"(acc[mi][ni][1]),
                          "+f"(acc[mi][ni][2]), "+f"(acc[mi][ni][3])
                        : "r"(afr[mi][0]), "r"(afr[mi][1]), "r"(afr[mi][2]), "r"(afr[mi][3]),
                          "r"(bfr[ni][0]), "r"(bfr[ni][1]));
                }
        }
        __syncthreads();
    }

    // Fused ON-LSTM epilogue. Columns gate-interleaved: col -> (j = col>>2, gate = col&3).
    const int lane4 = lane & 3;
    const bool evenl = (lane4 & 1) == 0;
    float* outH = d_out;
    float* outC = d_out + (size_t)BSZ * HID;
    int rbase = bm * 128 + warpM * 64;
#pragma unroll
    for (int mi = 0; mi < 4; mi++) {
        int r0 = rbase + mi * 16 + (lane >> 2);
#pragma unroll
        for (int ni = 0; ni < 8; ni++) {
            float p0 = __shfl_xor_sync(0xffffffffu, acc[mi][ni][0], 1);
            float p1 = __shfl_xor_sync(0xffffffffu, acc[mi][ni][1], 1);
            float p2 = __shfl_xor_sync(0xffffffffu, acc[mi][ni][2], 1);
            float p3 = __shfl_xor_sync(0xffffffffu, acc[mi][ni][3], 1);
            if (evenl) {
                int j  = (bn * 256 + warpN * 64 + ni * 8 + lane4 * 2) >> 2;
                int lv = j >> 4;
                {
                    float iv = sigmoidf_(acc[mi][ni][0]);
                    float fv = sigmoidf_(acc[mi][ni][1]);
                    float ov = sigmoidf_(p0);
                    float gv = tanhf(p1);
                    float cp = c_prev[(size_t)r0 * HID + j];
                    float ih = g_ih[(size_t)r0 * LVL + lv];
                    float fh = g_fh[(size_t)r0 * LVL + lv];
                    float w  = ih * fh;
                    float cn = w * (fv * cp + iv * gv) + (fh - w) * cp + (ih - w) * gv;
                    outC[(size_t)r0 * HID + j] = cn;
                    outH[(size_t)r0 * HID + j] = ov * tanhf(cn);
                }
                {
                    int r1 = r0 + 8;
                    float iv = sigmoidf_(acc[mi][ni][2]);
                    float fv = sigmoidf_(acc[mi][ni][3]);
                    float ov = sigmoidf_(p2);
                    float gv = tanhf(p3);
                    float cp = c_prev[(size_t)r1 * HID + j];
                    float ih = g_ih[(size_t)r1 * LVL + lv];
                    float fh = g_fh[(size_t)r1 * LVL + lv];
                    float w  = ih * fh;
                    float cn = w * (fv * cp + iv * gv) + (fh - w) * cp + (ih - w) * gv;
                    outC[(size_t)r1 * HID + j] = cn;
                    outH[(size_t)r1 * HID + j] = ov * tanhf(cn);
                }
            }
        }
    }
}

// ================= level GEMM: 128x128 tile, split-K over 4 slices =================
__global__ __launch_bounds__(256, 2) void gemm_level(void) {
    __shared__ __half As[2][128 * LDS];
    __shared__ __half Bs[2][128 * LDS];
    const int tid   = threadIdx.x;
    const int lane  = tid & 31;
    const int wid   = tid >> 5;
    const int warpM = wid >> 2;
    const int warpN = wid & 3;
    const int bm    = blockIdx.y;
    const int ks_id = blockIdx.x;             // K split 0..3
    const int kbase = ks_id * (KDIM / KSPLIT);

    const __half* Ag = g_A + (size_t)(bm * 128) * KDIM + kbase;
    const __half* Bg = g_W + (size_t)NGATE * KDIM + kbase;

    float acc[4][4][4];
#pragma unroll
    for (int a = 0; a < 4; a++)
#pragma unroll
        for (int b = 0; b < 4; b++)
#pragma unroll
            for (int c = 0; c < 4; c++) acc[a][b][c] = 0.0f;

    const int KT = (KDIM / KSPLIT) / 32;  // 16

    auto load_tile = [&](int buf, int kt) {
        int k0 = kt * 32;
#pragma unroll
        for (int i = 0; i < 2; i++) {
            int lin = tid + i * 256;
            int row = lin >> 2, ch = lin & 3;
            uint32_t da = smem_u32(&As[buf][row * LDS + ch * 8]);
            const __half* sa = Ag + (size_t)row * KDIM + k0 + ch * 8;
            asm volatile("cp.async.cg.shared.global [%0], [%1], 16;\n" ::"r"(da), "l"(sa));
            uint32_t db = smem_u32(&Bs[buf][row * LDS + ch * 8]);
            const __half* sb = Bg + (size_t)row * KDIM + k0 + ch * 8;
            asm volatile("cp.async.cg.shared.global [%0], [%1], 16;\n" ::"r"(db), "l"(sb));
        }
        asm volatile("cp.async.commit_group;\n");
    };

    load_tile(0, 0);
#pragma unroll 1
    for (int kt = 0; kt < KT; ++kt) {
        int buf = kt & 1;
        if (kt + 1 < KT) {
            load_tile(buf ^ 1, kt + 1);
            asm volatile("cp.async.wait_group 1;\n");
        } else {
            asm volatile("cp.async.wait_group 0;\n");
        }
        __syncthreads();
#pragma unroll
        for (int ks = 0; ks < 2; ++ks) {
            uint32_t afr[4][4];
#pragma unroll
            for (int mi = 0; mi < 4; ++mi) {
                int r  = warpM * 64 + mi * 16 + (lane & 15);
                int ch = ks * 2 + (lane >> 4);
                uint32_t addr = smem_u32(&As[buf][r * LDS + ch * 8]);
                asm volatile("ldmatrix.sync.aligned.m8n8.x4.shared.b16 {%0,%1,%2,%3}, [%4];"
                             : "=r"(afr[mi][0]), "=r"(afr[mi][1]), "=r"(afr[mi][2]), "=r"(afr[mi][3])
                             : "r"(addr));
            }
            uint32_t bfr[4][2];
#pragma unroll
            for (int np = 0; np < 2; ++np) {
                int r  = warpN * 32 + np * 16 + (lane & 15);
                int ch = ks * 2 + (lane >> 4);
                uint32_t addr = smem_u32(&Bs[buf][r * LDS + ch * 8]);
                uint32_t r0, r1, r2, r3;
                asm volatile("ldmatrix.sync.aligned.m8n8.x4.shared.b16 {%0,%1,%2,%3}, [%4];"
                             : "=r"(r0), "=r"(r1), "=r"(r2), "=r"(r3)
                             : "r"(addr));
                bfr[np * 2][0] = r0; bfr[np * 2 + 1][0] = r1;
                bfr[np * 2][1] = r2; bfr[np * 2 + 1][1] = r3;
            }
#pragma unroll
            for (int mi = 0; mi < 4; ++mi)
#pragma unroll
                for (int ni = 0; ni < 4; ++ni) {
                    asm volatile(
                        "mma.sync.aligned.m16n8k16.row.col.f32.f16.f16.f32 "
                        "{%0,%1,%2,%3}, {%4,%5,%6,%7}, {%8,%9}, {%0,%1,%2,%3};"
                        : "+f"(acc[mi][ni][0]), "+f"(acc[mi][ni][1]),
                          "+f"(acc[mi][ni][2]), "+f"(acc[mi][ni][3])
                        : "r"(afr[mi][0]), "r"(afr[mi][1]), "r"(afr[mi][2]), "r"(afr[mi][3]),
                          "r"(bfr[ni][0]), "r"(bfr[ni][1]));
                }
        }
        __syncthreads();
    }

    float* Ldst = g_lev[ks_id];
    int rbase = bm * 128 + warpM * 64;
#pragma unroll
    for (int mi = 0; mi < 4; mi++) {
        int r0 = rbase + mi * 16 + (lane >> 2);
#pragma unroll
        for (int ni = 0; ni < 4; ni++) {
            int c0 = warpN * 32 + ni * 8 + (lane & 3) * 2;
            Ldst[(size_t)r0 * NLEV + c0]           = acc[mi][ni][0];
            Ldst[(size_t)r0 * NLEV + c0 + 1]       = acc[mi][ni][1];
            Ldst[(size_t)(r0 + 8) * NLEV + c0]     = acc[mi][ni][2];
            Ldst[(size_t)(r0 + 8) * NLEV + c0 + 1] = acc[mi][ni][3];
        }
    }
}

// -------- per-row: sum split-K partials, softmax + cumsum over 64 levels --------
__global__ void level_kernel() {
    int row  = blockIdx.x * 8 + (threadIdx.x >> 5);
    int lane = threadIdx.x & 31;
    float xi0 = 0.f, xi1 = 0.f, xf0 = 0.f, xf1 = 0.f;
#pragma unroll
    for (int s = 0; s < KSPLIT; s++) {
        const float* L = g_lev[s] + (size_t)row * NLEV;
        xi0 += L[lane];      xi1 += L[32 + lane];
        xf0 += L[64 + lane]; xf1 += L[96 + lane];
    }

    // ---- i_h = forward inclusive cumsum of softmax(cc_f_h) ----
    float m = fmaxf(xf0, xf1);
#pragma unroll
    for (int o = 16; o; o >>= 1) m = fmaxf(m, __shfl_xor_sync(~0u, m, o));
    float e0 = __expf(xf0 - m), e1 = __expf(xf1 - m);
    float s = e0 + e1;
#pragma unroll
    for (int o = 16; o; o >>= 1) s += __shfl_xor_sync(~0u, s, o);
    float inv = 1.0f / s;
    float s0 = e0;
#pragma unroll
    for (int o = 1; o < 32; o <<= 1) { float v = __shfl_up_sync(~0u, s0, o); if (lane >= o) s0 += v; }
    float tot0 = __shfl_sync(~0u, s0, 31);
    float s1 = e1;
#pragma unroll
    for (int o = 1; o < 32; o <<= 1) { float v = __shfl_up_sync(~0u, s1, o); if (lane >= o) s1 += v; }
    g_ih[(size_t)row * LVL + lane]      = s0 * inv;
    g_ih[(size_t)row * LVL + 32 + lane] = (tot0 + s1) * inv;

    // ---- f_h = reverse inclusive cumsum of softmax(cc_i_h) ----
    float mq = fmaxf(xi0, xi1);
#pragma unroll
    for (int o = 16; o; o >>= 1) mq = fmaxf(mq, __shfl_xor_sync(~0u, mq, o));
    float q0 = __expf(xi0 - mq), q1 = __expf(xi1 - mq);
    float sq = q0 + q1;
#pragma unroll
    for (int o = 16; o; o >>= 1) sq += __shfl_xor_sync(~0u, sq, o);
    float invq = 1.0f / sq;
    float r1 = q1;
#pragma unroll
    for (int o = 1; o < 32; o <<= 1) { float v = __shfl_down_sync(~0u, r1, o); if (lane < 32 - o) r1 += v; }
    float tot1 = __shfl_sync(~0u, r1, 0);
    float r0 = q0;
#pragma unroll
    for (int o = 1; o < 32; o <<= 1) { float v = __shfl_down_sync(~0u, r0, o); if (lane < 32 - o) r0 += v; }
    g_fh[(size_t)row * LVL + lane]      = (r0 + tot1) * invq;
    g_fh[(size_t)row * LVL + 32 + lane] = r1 * invq;
}

extern "C" void kernel_launch(void* const* d_in, const int* in_sizes, int n_in,
                              void* d_out, int out_size) {
    const float* input   = (const float*)d_in[0];
    const float* h_prev  = (const float*)d_in[1];
    const float* c_prev  = (const float*)d_in[2];
    const float* W_lstm  = (const float*)d_in[3];
    const float* W_level = (const float*)d_in[4];
    float* out = (float*)d_out;

    const int smem_main = (4 * 5120 + 4 * 10240) * 2;  // 122880 B
    cudaFuncSetAttribute(gemm_main, cudaFuncAttributeMaxDynamicSharedMemorySize, smem_main);

    prep_A<<<(BSZ * KDIM / 4) / 256, 256>>>(input, h_prev);
    prep_W<<<((NGATE + NLEV) * (KDIM / 4)) / 256, 256>>>(W_lstm, W_level);
    gemm_level<<<dim3(KSPLIT, BSZ / 128), 256>>>();                       // level logits (split-K)
    level_kernel<<<BSZ / 8, 256>>>();                                     // softmax + cumsum
    gemm_main<<<dim3(NGATE / 256, BSZ / 128), 256, smem_main>>>(c_prev, out); // gates + epilogue
}

// round 11
// speedup vs baseline: 1.2175x; 1.2175x over previous
#include <cuda_runtime.h>
#include <cuda_fp16.h>
#include <cstdint>

#define BSZ   8192
#define HID   1024
#define KDIM  2048
#define LVL   64
#define NGATE 4096
#define NLEV  128
#define KSPLIT 4

// -------- scratch (static __device__, no allocations) --------
__device__ __half g_A[(size_t)BSZ * KDIM];            // fp16 combined input
__device__ __half g_W[(size_t)(NGATE + NLEV) * KDIM]; // fp16 reordered weights
__device__ float  g_lev[KSPLIT][(size_t)BSZ * NLEV];  // level logit partials (split-K)
__device__ float  g_ih[(size_t)BSZ * LVL];
__device__ float  g_fh[(size_t)BSZ * LVL];

__device__ __forceinline__ float sigmoidf_(float x) { return 1.0f / (1.0f + __expf(-x)); }
__device__ __forceinline__ uint32_t smem_u32(const void* p) {
    return (uint32_t)__cvta_generic_to_shared(p);
}

// -------- prep: fp32 -> fp16 combined activation --------
__global__ void prep_A(const float* __restrict__ inp, const float* __restrict__ hprev) {
    int idx = blockIdx.x * blockDim.x + threadIdx.x;   // float4 index, 512 per row
    int row = idx >> 9;
    int c4  = idx & 511;
    const float* src = (c4 < 256) ? (inp + (size_t)row * 1024 + c4 * 4)
                                  : (hprev + (size_t)row * 1024 + (c4 - 256) * 4);
    float4 v = *reinterpret_cast<const float4*>(src);
    __half2* dst = reinterpret_cast<__half2*>(g_A + (size_t)row * KDIM + c4 * 4);
    dst[0] = __floats2half2_rn(v.x, v.y);
    dst[1] = __floats2half2_rn(v.z, v.w);
}

// -------- prep: fp32 -> fp16 weights, gate-interleaved rows --------
__global__ void prep_W(const float* __restrict__ wl, const float* __restrict__ wv) {
    int idx = blockIdx.x * blockDim.x + threadIdx.x;   // float4 index
    int n  = idx >> 9;
    int c4 = idx & 511;
    const float* src;
    if (n < NGATE) src = wl + (size_t)((n & 3) * 1024 + (n >> 2)) * KDIM + c4 * 4;
    else           src = wv + (size_t)(n - NGATE) * KDIM + c4 * 4;
    float4 v = *reinterpret_cast<const float4*>(src);
    __half2* dst = reinterpret_cast<__half2*>(g_W + (size_t)n * KDIM + c4 * 4);
    dst[0] = __floats2half2_rn(v.x, v.y);
    dst[1] = __floats2half2_rn(v.z, v.w);
}

#define BM 128
#define BN 128
#define BK 32
#define LDS 40   // padded half stride (80B) -> conflict-free ldmatrix

// ================= main GEMM: 128x128, 2-stage double buffer (proven R1 config) =================
__global__ __launch_bounds__(256, 2) void gemm_main(const float* __restrict__ c_prev,
                                                    float* __restrict__ d_out) {
    __shared__ __half As[2][BM * LDS];
    __shared__ __half Bs[2][BM * LDS];
    const int tid   = threadIdx.x;
    const int lane  = tid & 31;
    const int wid   = tid >> 5;
    const int warpM = wid >> 2;   // 0..1 (64 rows each)
    const int warpN = wid & 3;    // 0..3 (32 cols each)
    const int bm    = blockIdx.y;
    const int bn    = blockIdx.x;

    const __half* Ag = g_A + (size_t)(bm * BM) * KDIM;
    const __half* Bg = g_W + (size_t)(bn * BN) * KDIM;

    float acc[4][4][4];
#pragma unroll
    for (int a = 0; a < 4; a++)
#pragma unroll
        for (int b = 0; b < 4; b++)
#pragma unroll
            for (int c = 0; c < 4; c++) acc[a][b][c] = 0.0f;

    const int KT = KDIM / BK;  // 64

    auto load_tile = [&](int buf, int kt) {
        int k0 = kt * BK;
#pragma unroll
        for (int i = 0; i < 2; i++) {
            int lin = tid + i * 256;
            int row = lin >> 2, ch = lin & 3;
            uint32_t da = smem_u32(&As[buf][row * LDS + ch * 8]);
            const __half* sa = Ag + (size_t)row * KDIM + k0 + ch * 8;
            asm volatile("cp.async.cg.shared.global [%0], [%1], 16;\n" ::"r"(da), "l"(sa));
            uint32_t db = smem_u32(&Bs[buf][row * LDS + ch * 8]);
            const __half* sb = Bg + (size_t)row * KDIM + k0 + ch * 8;
            asm volatile("cp.async.cg.shared.global [%0], [%1], 16;\n" ::"r"(db), "l"(sb));
        }
        asm volatile("cp.async.commit_group;\n");
    };

    load_tile(0, 0);
#pragma unroll 1
    for (int kt = 0; kt < KT; ++kt) {
        int buf = kt & 1;
        if (kt + 1 < KT) {
            load_tile(buf ^ 1, kt + 1);
            asm volatile("cp.async.wait_group 1;\n");
        } else {
            asm volatile("cp.async.wait_group 0;\n");
        }
        __syncthreads();
#pragma unroll
        for (int ks = 0; ks < 2; ++ks) {
            uint32_t afr[4][4];
#pragma unroll
            for (int mi = 0; mi < 4; ++mi) {
                int r  = warpM * 64 + mi * 16 + (lane & 15);
                int ch = ks * 2 + (lane >> 4);
                uint32_t addr = smem_u32(&As[buf][r * LDS + ch * 8]);
                asm volatile("ldmatrix.sync.aligned.m8n8.x4.shared.b16 {%0,%1,%2,%3}, [%4];"
                             : "=r"(afr[mi][0]), "=r"(afr[mi][1]), "=r"(afr[mi][2]), "=r"(afr[mi][3])
                             : "r"(addr));
            }
            uint32_t bfr[4][2];
#pragma unroll
            for (int np = 0; np < 2; ++np) {
                int r  = warpN * 32 + np * 16 + (lane & 15);
                int ch = ks * 2 + (lane >> 4);
                uint32_t addr = smem_u32(&Bs[buf][r * LDS + ch * 8]);
                uint32_t r0, r1, r2, r3;
                asm volatile("ldmatrix.sync.aligned.m8n8.x4.shared.b16 {%0,%1,%2,%3}, [%4];"
                             : "=r"(r0), "=r"(r1), "=r"(r2), "=r"(r3)
                             : "r"(addr));
                bfr[np * 2][0] = r0; bfr[np * 2 + 1][0] = r1;
                bfr[np * 2][1] = r2; bfr[np * 2 + 1][1] = r3;
            }
#pragma unroll
            for (int mi = 0; mi < 4; ++mi)
#pragma unroll
                for (int ni = 0; ni < 4; ++ni) {
                    asm volatile(
                        "mma.sync.aligned.m16n8k16.row.col.f32.f16.f16.f32 "
                        "{%0,%1,%2,%3}, {%4,%5,%6,%7}, {%8,%9}, {%0,%1,%2,%3};"
                        : "+f"(acc[mi][ni][0]), "+f"(acc[mi][ni][1]),
                          "+f"(acc[mi][ni][2]), "+f"(acc[mi][ni][3])
                        : "r"(afr[mi][0]), "r"(afr[mi][1]), "r"(afr[mi][2]), "r"(afr[mi][3]),
                          "r"(bfr[ni][0]), "r"(bfr[ni][1]));
                }
        }
        __syncthreads();
    }

    // Fused ON-LSTM epilogue. Columns gate-interleaved: col -> (j = col>>2, gate = col&3).
    const int lane4 = lane & 3;
    const bool evenl = (lane4 & 1) == 0;
    float* outH = d_out;
    float* outC = d_out + (size_t)BSZ * HID;
    int rbase = bm * BM + warpM * 64;
#pragma unroll
    for (int mi = 0; mi < 4; mi++) {
        int r0 = rbase + mi * 16 + (lane >> 2);
#pragma unroll
        for (int ni = 0; ni < 4; ni++) {
            float p0 = __shfl_xor_sync(0xffffffffu, acc[mi][ni][0], 1);
            float p1 = __shfl_xor_sync(0xffffffffu, acc[mi][ni][1], 1);
            float p2 = __shfl_xor_sync(0xffffffffu, acc[mi][ni][2], 1);
            float p3 = __shfl_xor_sync(0xffffffffu, acc[mi][ni][3], 1);
            if (evenl) {
                int j  = (bn * BN + warpN * 32 + ni * 8 + lane4 * 2) >> 2;
                int lv = j >> 4;
                {
                    float iv = sigmoidf_(acc[mi][ni][0]);
                    float fv = sigmoidf_(acc[mi][ni][1]);
                    float ov = sigmoidf_(p0);
                    float gv = tanhf(p1);
                    float cp = c_prev[(size_t)r0 * HID + j];
                    float ih = g_ih[(size_t)r0 * LVL + lv];
                    float fh = g_fh[(size_t)r0 * LVL + lv];
                    float w  = ih * fh;
                    float cn = w * (fv * cp + iv * gv) + (fh - w) * cp + (ih - w) * gv;
                    outC[(size_t)r0 * HID + j] = cn;
                    outH[(size_t)r0 * HID + j] = ov * tanhf(cn);
                }
                {
                    int r1 = r0 + 8;
                    float iv = sigmoidf_(acc[mi][ni][2]);
                    float fv = sigmoidf_(acc[mi][ni][3]);
                    float ov = sigmoidf_(p2);
                    float gv = tanhf(p3);
                    float cp = c_prev[(size_t)r1 * HID + j];
                    float ih = g_ih[(size_t)r1 * LVL + lv];
                    float fh = g_fh[(size_t)r1 * LVL + lv];
                    float w  = ih * fh;
                    float cn = w * (fv * cp + iv * gv) + (fh - w) * cp + (ih - w) * gv;
                    outC[(size_t)r1 * HID + j] = cn;
                    outH[(size_t)r1 * HID + j] = ov * tanhf(cn);
                }
            }
        }
    }
}

// ================= level GEMM: 128x128 tile, split-K over 4 slices =================
__global__ __launch_bounds__(256, 2) void gemm_level(void) {
    __shared__ __half As[2][BM * LDS];
    __shared__ __half Bs[2][BM * LDS];
    const int tid   = threadIdx.x;
    const int lane  = tid & 31;
    const int wid   = tid >> 5;
    const int warpM = wid >> 2;
    const int warpN = wid & 3;
    const int bm    = blockIdx.y;
    const int ks_id = blockIdx.x;             // K split 0..3
    const int kbase = ks_id * (KDIM / KSPLIT);

    const __half* Ag = g_A + (size_t)(bm * BM) * KDIM + kbase;
    const __half* Bg = g_W + (size_t)NGATE * KDIM + kbase;

    float acc[4][4][4];
#pragma unroll
    for (int a = 0; a < 4; a++)
#pragma unroll
        for (int b = 0; b < 4; b++)
#pragma unroll
            for (int c = 0; c < 4; c++) acc[a][b][c] = 0.0f;

    const int KT = (KDIM / KSPLIT) / BK;  // 16

    auto load_tile = [&](int buf, int kt) {
        int k0 = kt * BK;
#pragma unroll
        for (int i = 0; i < 2; i++) {
            int lin = tid + i * 256;
            int row = lin >> 2, ch = lin & 3;
            uint32_t da = smem_u32(&As[buf][row * LDS + ch * 8]);
            const __half* sa = Ag + (size_t)row * KDIM + k0 + ch * 8;
            asm volatile("cp.async.cg.shared.global [%0], [%1], 16;\n" ::"r"(da), "l"(sa));
            uint32_t db = smem_u32(&Bs[buf][row * LDS + ch * 8]);
            const __half* sb = Bg + (size_t)row * KDIM + k0 + ch * 8;
            asm volatile("cp.async.cg.shared.global [%0], [%1], 16;\n" ::"r"(db), "l"(sb));
        }
        asm volatile("cp.async.commit_group;\n");
    };

    load_tile(0, 0);
#pragma unroll 1
    for (int kt = 0; kt < KT; ++kt) {
        int buf = kt & 1;
        if (kt + 1 < KT) {
            load_tile(buf ^ 1, kt + 1);
            asm volatile("cp.async.wait_group 1;\n");
        } else {
            asm volatile("cp.async.wait_group 0;\n");
        }
        __syncthreads();
#pragma unroll
        for (int ks = 0; ks < 2; ++ks) {
            uint32_t afr[4][4];
#pragma unroll
            for (int mi = 0; mi < 4; ++mi) {
                int r  = warpM * 64 + mi * 16 + (lane & 15);
                int ch = ks * 2 + (lane >> 4);
                uint32_t addr = smem_u32(&As[buf][r * LDS + ch * 8]);
                asm volatile("ldmatrix.sync.aligned.m8n8.x4.shared.b16 {%0,%1,%2,%3}, [%4];"
                             : "=r"(afr[mi][0]), "=r"(afr[mi][1]), "=r"(afr[mi][2]), "=r"(afr[mi][3])
                             : "r"(addr));
            }
            uint32_t bfr[4][2];
#pragma unroll
            for (int np = 0; np < 2; ++np) {
                int r  = warpN * 32 + np * 16 + (lane & 15);
                int ch = ks * 2 + (lane >> 4);
                uint32_t addr = smem_u32(&Bs[buf][r * LDS + ch * 8]);
                uint32_t r0, r1, r2, r3;
                asm volatile("ldmatrix.sync.aligned.m8n8.x4.shared.b16 {%0,%1,%2,%3}, [%4];"
                             : "=r"(r0), "=r"(r1), "=r"(r2), "=r"(r3)
                             : "r"(addr));
                bfr[np * 2][0] = r0; bfr[np * 2 + 1][0] = r1;
                bfr[np * 2][1] = r2; bfr[np * 2 + 1][1] = r3;
            }
#pragma unroll
            for (int mi = 0; mi < 4; ++mi)
#pragma unroll
                for (int ni = 0; ni < 4; ++ni) {
                    asm volatile(
                        "mma.sync.aligned.m16n8k16.row.col.f32.f16.f16.f32 "
                        "{%0,%1,%2,%3}, {%4,%5,%6,%7}, {%8,%9}, {%0,%1,%2,%3};"
                        : "+f"(acc[mi][ni][0]), "+f"(acc[mi][ni][1]),
                          "+f"(acc[mi][ni][2]), "+f"(acc[mi][ni][3])
                        : "r"(afr[mi][0]), "r"(afr[mi][1]), "r"(afr[mi][2]), "r"(afr[mi][3]),
                          "r"(bfr[ni][0]), "r"(bfr[ni][1]));
                }
        }
        __syncthreads();
    }

    float* Ldst = g_lev[ks_id];
    int rbase = bm * BM + warpM * 64;
#pragma unroll
    for (int mi = 0; mi < 4; mi++) {
        int r0 = rbase + mi * 16 + (lane >> 2);
#pragma unroll
        for (int ni = 0; ni < 4; ni++) {
            int c0 = warpN * 32 + ni * 8 + (lane & 3) * 2;
            Ldst[(size_t)r0 * NLEV + c0]           = acc[mi][ni][0];
            Ldst[(size_t)r0 * NLEV + c0 + 1]       = acc[mi][ni][1];
            Ldst[(size_t)(r0 + 8) * NLEV + c0]     = acc[mi][ni][2];
            Ldst[(size_t)(r0 + 8) * NLEV + c0 + 1] = acc[mi][ni][3];
        }
    }
}

// -------- per-row: sum split-K partials, softmax + cumsum over 64 levels --------
__global__ void level_kernel() {
    int row  = blockIdx.x * 8 + (threadIdx.x >> 5);
    int lane = threadIdx.x & 31;
    float xi0 = 0.f, xi1 = 0.f, xf0 = 0.f, xf1 = 0.f;
#pragma unroll
    for (int s = 0; s < KSPLIT; s++) {
        const float* L = g_lev[s] + (size_t)row * NLEV;
        xi0 += L[lane];      xi1 += L[32 + lane];
        xf0 += L[64 + lane]; xf1 += L[96 + lane];
    }

    // ---- i_h = forward inclusive cumsum of softmax(cc_f_h) ----
    float m = fmaxf(xf0, xf1);
#pragma unroll
    for (int o = 16; o; o >>= 1) m = fmaxf(m, __shfl_xor_sync(~0u, m, o));
    float e0 = __expf(xf0 - m), e1 = __expf(xf1 - m);
    float s = e0 + e1;
#pragma unroll
    for (int o = 16; o; o >>= 1) s += __shfl_xor_sync(~0u, s, o);
    float inv = 1.0f / s;
    float s0 = e0;
#pragma unroll
    for (int o = 1; o < 32; o <<= 1) { float v = __shfl_up_sync(~0u, s0, o); if (lane >= o) s0 += v; }
    float tot0 = __shfl_sync(~0u, s0, 31);
    float s1 = e1;
#pragma unroll
    for (int o = 1; o < 32; o <<= 1) { float v = __shfl_up_sync(~0u, s1, o); if (lane >= o) s1 += v; }
    g_ih[(size_t)row * LVL + lane]      = s0 * inv;
    g_ih[(size_t)row * LVL + 32 + lane] = (tot0 + s1) * inv;

    // ---- f_h = reverse inclusive cumsum of softmax(cc_i_h) ----
    float mq = fmaxf(xi0, xi1);
#pragma unroll
    for (int o = 16; o; o >>= 1) mq = fmaxf(mq, __shfl_xor_sync(~0u, mq, o));
    float q0 = __expf(xi0 - mq), q1 = __expf(xi1 - mq);
    float sq = q0 + q1;
#pragma unroll
    for (int o = 16; o; o >>= 1) sq += __shfl_xor_sync(~0u, sq, o);
    float invq = 1.0f / sq;
    float r1 = q1;
#pragma unroll
    for (int o = 1; o < 32; o <<= 1) { float v = __shfl_down_sync(~0u, r1, o); if (lane < 32 - o) r1 += v; }
    float tot1 = __shfl_sync(~0u, r1, 0);
    float r0 = q0;
#pragma unroll
    for (int o = 1; o < 32; o <<= 1) { float v = __shfl_down_sync(~0u, r0, o); if (lane < 32 - o) r0 += v; }
    g_fh[(size_t)row * LVL + lane]      = (r0 + tot1) * invq;
    g_fh[(size_t)row * LVL + 32 + lane] = r1 * invq;
}

extern "C" void kernel_launch(void* const* d_in, const int* in_sizes, int n_in,
                              void* d_out, int out_size) {
    const float* input   = (const float*)d_in[0];
    const float* h_prev  = (const float*)d_in[1];
    const float* c_prev  = (const float*)d_in[2];
    const float* W_lstm  = (const float*)d_in[3];
    const float* W_level = (const float*)d_in[4];
    float* out = (float*)d_out;

    prep_A<<<(BSZ * KDIM / 4) / 256, 256>>>(input, h_prev);
    prep_W<<<((NGATE + NLEV) * (KDIM / 4)) / 256, 256>>>(W_lstm, W_level);
    gemm_level<<<dim3(KSPLIT, BSZ / 128), 256>>>();                       // level logits (split-K)
    level_kernel<<<BSZ / 8, 256>>>();                                     // softmax + cumsum
    gemm_main<<<dim3(NGATE / BN, BSZ / BM), 256>>>(c_prev, out);          // gates + epilogue
}

// round 12
// speedup vs baseline: 1.2195x; 1.0017x over previous
#include <cuda_runtime.h>
#include <cuda_fp16.h>
#include <cstdint>

#define BSZ   8192
#define HID   1024
#define KDIM  2048
#define LVL   64
#define NGATE 4096
#define NLEV  128
#define KSPLIT 4

// -------- scratch (static __device__, no allocations) --------
__device__ __half g_A[(size_t)BSZ * KDIM];            // fp16 combined input
__device__ __half g_W[(size_t)(NGATE + NLEV) * KDIM]; // fp16 reordered weights
__device__ float  g_lev[KSPLIT][(size_t)BSZ * NLEV];  // level logit partials (split-K)
__device__ float  g_ih[(size_t)BSZ * LVL];
__device__ float  g_fh[(size_t)BSZ * LVL];

__device__ __forceinline__ float sigmoidf_(float x) { return 1.0f / (1.0f + __expf(-x)); }
__device__ __forceinline__ uint32_t smem_u32(const void* p) {
    return (uint32_t)__cvta_generic_to_shared(p);
}

// -------- merged prep: fp32 -> fp16 for A (combined) and W (gate-interleaved) --------
// One launch; also shifts gemm_main to launch index 3 (the ncu capture slot).
#define A4CNT (BSZ * 512)                      // float4 chunks in A
#define W4CNT ((NGATE + NLEV) * 512)           // float4 chunks in W
__global__ void prep_all(const float* __restrict__ inp, const float* __restrict__ hprev,
                         const float* __restrict__ wl, const float* __restrict__ wv) {
    int idx = blockIdx.x * blockDim.x + threadIdx.x;
    if (idx < A4CNT) {
        int row = idx >> 9;
        int c4  = idx & 511;
        const float* src = (c4 < 256) ? (inp + (size_t)row * 1024 + c4 * 4)
                                      : (hprev + (size_t)row * 1024 + (c4 - 256) * 4);
        float4 v = *reinterpret_cast<const float4*>(src);
        __half2* dst = reinterpret_cast<__half2*>(g_A + (size_t)row * KDIM + c4 * 4);
        dst[0] = __floats2half2_rn(v.x, v.y);
        dst[1] = __floats2half2_rn(v.z, v.w);
    } else if (idx < A4CNT + W4CNT) {
        int j  = idx - A4CNT;
        int n  = j >> 9;
        int c4 = j & 511;
        const float* src;
        if (n < NGATE) src = wl + (size_t)((n & 3) * 1024 + (n >> 2)) * KDIM + c4 * 4;
        else           src = wv + (size_t)(n - NGATE) * KDIM + c4 * 4;
        float4 v = *reinterpret_cast<const float4*>(src);
        __half2* dst = reinterpret_cast<__half2*>(g_W + (size_t)n * KDIM + c4 * 4);
        dst[0] = __floats2half2_rn(v.x, v.y);
        dst[1] = __floats2half2_rn(v.z, v.w);
    }
}

#define BM 128
#define BN 128
#define BK 32
#define LDS 40       // padded half stride (80B) -> conflict-free ldmatrix
#define STG 5120     // halves per stage per operand (128*40)

// ================= main GEMM: 128x128, 3-stage cp.async, single sync/iter =================
__global__ __launch_bounds__(256, 2) void gemm_main(const float* __restrict__ c_prev,
                                                    float* __restrict__ d_out) {
    extern __shared__ __half sm[];
    __half* Asm = sm;               // 3 stages x STG
    __half* Bsm = sm + 3 * STG;     // 3 stages x STG

    const int tid   = threadIdx.x;
    const int lane  = tid & 31;
    const int wid   = tid >> 5;
    const int warpM = wid >> 2;   // 0..1 (64 rows each)
    const int warpN = wid & 3;    // 0..3 (32 cols each)
    const int bm    = blockIdx.y;
    const int bn    = blockIdx.x;

    const __half* Ag = g_A + (size_t)(bm * BM) * KDIM;
    const __half* Bg = g_W + (size_t)(bn * BN) * KDIM;

    float acc[4][4][4];
#pragma unroll
    for (int a = 0; a < 4; a++)
#pragma unroll
        for (int b = 0; b < 4; b++)
#pragma unroll
            for (int c = 0; c < 4; c++) acc[a][b][c] = 0.0f;

    const int KT = KDIM / BK;  // 64

    auto load_stage = [&](int s) {
        int buf = s % 3;
        int k0  = s * BK;
        __half* A = Asm + buf * STG;
        __half* B = Bsm + buf * STG;
#pragma unroll
        for (int i = 0; i < 2; i++) {
            int lin = tid + i * 256;
            int row = lin >> 2, ch = lin & 3;
            uint32_t da = smem_u32(A + row * LDS + ch * 8);
            const __half* sa = Ag + (size_t)row * KDIM + k0 + ch * 8;
            asm volatile("cp.async.cg.shared.global [%0], [%1], 16;\n" ::"r"(da), "l"(sa));
            uint32_t db = smem_u32(B + row * LDS + ch * 8);
            const __half* sb = Bg + (size_t)row * KDIM + k0 + ch * 8;
            asm volatile("cp.async.cg.shared.global [%0], [%1], 16;\n" ::"r"(db), "l"(sb));
        }
        asm volatile("cp.async.commit_group;\n");
    };

    load_stage(0);
    load_stage(1);

#pragma unroll 1
    for (int kt = 0; kt < KT; ++kt) {
        if (kt == KT - 1) asm volatile("cp.async.wait_group 0;\n");
        else              asm volatile("cp.async.wait_group 1;\n");
        __syncthreads();
        if (kt + 2 < KT) load_stage(kt + 2);   // prefetch into the stage freed at kt-1

        int buf = kt % 3;
        const __half* As = Asm + buf * STG;
        const __half* Bs = Bsm + buf * STG;
#pragma unroll
        for (int ks = 0; ks < 2; ++ks) {
            uint32_t afr[4][4];
#pragma unroll
            for (int mi = 0; mi < 4; ++mi) {
                int r  = warpM * 64 + mi * 16 + (lane & 15);
                int ch = ks * 2 + (lane >> 4);
                uint32_t addr = smem_u32(As + r * LDS + ch * 8);
                asm volatile("ldmatrix.sync.aligned.m8n8.x4.shared.b16 {%0,%1,%2,%3}, [%4];"
                             : "=r"(afr[mi][0]), "=r"(afr[mi][1]), "=r"(afr[mi][2]), "=r"(afr[mi][3])
                             : "r"(addr));
            }
            uint32_t bfr[4][2];
#pragma unroll
            for (int np = 0; np < 2; ++np) {
                int r  = warpN * 32 + np * 16 + (lane & 15);
                int ch = ks * 2 + (lane >> 4);
                uint32_t addr = smem_u32(Bs + r * LDS + ch * 8);
                uint32_t r0, r1, r2, r3;
                asm volatile("ldmatrix.sync.aligned.m8n8.x4.shared.b16 {%0,%1,%2,%3}, [%4];"
                             : "=r"(r0), "=r"(r1), "=r"(r2), "=r"(r3)
                             : "r"(addr));
                bfr[np * 2][0] = r0; bfr[np * 2 + 1][0] = r1;
                bfr[np * 2][1] = r2; bfr[np * 2 + 1][1] = r3;
            }
#pragma unroll
            for (int mi = 0; mi < 4; ++mi)
#pragma unroll
                for (int ni = 0; ni < 4; ++ni) {
                    asm volatile(
                        "mma.sync.aligned.m16n8k16.row.col.f32.f16.f16.f32 "
                        "{%0,%1,%2,%3}, {%4,%5,%6,%7}, {%8,%9}, {%0,%1,%2,%3};"
                        : "+f"(acc[mi][ni][0]), "+f"(acc[mi][ni][1]),
                          "+f"(acc[mi][ni][2]), "+f"(acc[mi][ni][3])
                        : "r"(afr[mi][0]), "r"(afr[mi][1]), "r"(afr[mi][2]), "r"(afr[mi][3]),
                          "r"(bfr[ni][0]), "r"(bfr[ni][1]));
                }
        }
    }

    // Fused ON-LSTM epilogue. Columns gate-interleaved: col -> (j = col>>2, gate = col&3).
    const int lane4 = lane & 3;
    const bool evenl = (lane4 & 1) == 0;
    float* outH = d_out;
    float* outC = d_out + (size_t)BSZ * HID;
    int rbase = bm * BM + warpM * 64;
#pragma unroll
    for (int mi = 0; mi < 4; mi++) {
        int r0 = rbase + mi * 16 + (lane >> 2);
#pragma unroll
        for (int ni = 0; ni < 4; ni++) {
            float p0 = __shfl_xor_sync(0xffffffffu, acc[mi][ni][0], 1);
            float p1 = __shfl_xor_sync(0xffffffffu, acc[mi][ni][1], 1);
            float p2 = __shfl_xor_sync(0xffffffffu, acc[mi][ni][2], 1);
            float p3 = __shfl_xor_sync(0xffffffffu, acc[mi][ni][3], 1);
            if (evenl) {
                int j  = (bn * BN + warpN * 32 + ni * 8 + lane4 * 2) >> 2;
                int lv = j >> 4;
                {
                    float iv = sigmoidf_(acc[mi][ni][0]);
                    float fv = sigmoidf_(acc[mi][ni][1]);
                    float ov = sigmoidf_(p0);
                    float gv = tanhf(p1);
                    float cp = c_prev[(size_t)r0 * HID + j];
                    float ih = g_ih[(size_t)r0 * LVL + lv];
                    float fh = g_fh[(size_t)r0 * LVL + lv];
                    float w  = ih * fh;
                    float cn = w * (fv * cp + iv * gv) + (fh - w) * cp + (ih - w) * gv;
                    outC[(size_t)r0 * HID + j] = cn;
                    outH[(size_t)r0 * HID + j] = ov * tanhf(cn);
                }
                {
                    int r1 = r0 + 8;
                    float iv = sigmoidf_(acc[mi][ni][2]);
                    float fv = sigmoidf_(acc[mi][ni][3]);
                    float ov = sigmoidf_(p2);
                    float gv = tanhf(p3);
                    float cp = c_prev[(size_t)r1 * HID + j];
                    float ih = g_ih[(size_t)r1 * LVL + lv];
                    float fh = g_fh[(size_t)r1 * LVL + lv];
                    float w  = ih * fh;
                    float cn = w * (fv * cp + iv * gv) + (fh - w) * cp + (ih - w) * gv;
                    outC[(size_t)r1 * HID + j] = cn;
                    outH[(size_t)r1 * HID + j] = ov * tanhf(cn);
                }
            }
        }
    }
}

// ================= level GEMM: 128x128 tile, split-K over 4 slices (unchanged) =================
__global__ __launch_bounds__(256, 2) void gemm_level(void) {
    __shared__ __half As[2][BM * LDS];
    __shared__ __half Bs[2][BM * LDS];
    const int tid   = threadIdx.x;
    const int lane  = tid & 31;
    const int wid   = tid >> 5;
    const int warpM = wid >> 2;
    const int warpN = wid & 3;
    const int bm    = blockIdx.y;
    const int ks_id = blockIdx.x;             // K split 0..3
    const int kbase = ks_id * (KDIM / KSPLIT);

    const __half* Ag = g_A + (size_t)(bm * BM) * KDIM + kbase;
    const __half* Bg = g_W + (size_t)NGATE * KDIM + kbase;

    float acc[4][4][4];
#pragma unroll
    for (int a = 0; a < 4; a++)
#pragma unroll
        for (int b = 0; b < 4; b++)
#pragma unroll
            for (int c = 0; c < 4; c++) acc[a][b][c] = 0.0f;

    const int KT = (KDIM / KSPLIT) / BK;  // 16

    auto load_tile = [&](int buf, int kt) {
        int k0 = kt * BK;
#pragma unroll
        for (int i = 0; i < 2; i++) {
            int lin = tid + i * 256;
            int row = lin >> 2, ch = lin & 3;
            uint32_t da = smem_u32(&As[buf][row * LDS + ch * 8]);
            const __half* sa = Ag + (size_t)row * KDIM + k0 + ch * 8;
            asm volatile("cp.async.cg.shared.global [%0], [%1], 16;\n" ::"r"(da), "l"(sa));
            uint32_t db = smem_u32(&Bs[buf][row * LDS + ch * 8]);
            const __half* sb = Bg + (size_t)row * KDIM + k0 + ch * 8;
            asm volatile("cp.async.cg.shared.global [%0], [%1], 16;\n" ::"r"(db), "l"(sb));
        }
        asm volatile("cp.async.commit_group;\n");
    };

    load_tile(0, 0);
#pragma unroll 1
    for (int kt = 0; kt < KT; ++kt) {
        int buf = kt & 1;
        if (kt + 1 < KT) {
            load_tile(buf ^ 1, kt + 1);
            asm volatile("cp.async.wait_group 1;\n");
        } else {
            asm volatile("cp.async.wait_group 0;\n");
        }
        __syncthreads();
#pragma unroll
        for (int ks = 0; ks < 2; ++ks) {
            uint32_t afr[4][4];
#pragma unroll
            for (int mi = 0; mi < 4; ++mi) {
                int r  = warpM * 64 + mi * 16 + (lane & 15);
                int ch = ks * 2 + (lane >> 4);
                uint32_t addr = smem_u32(&As[buf][r * LDS + ch * 8]);
                asm volatile("ldmatrix.sync.aligned.m8n8.x4.shared.b16 {%0,%1,%2,%3}, [%4];"
                             : "=r"(afr[mi][0]), "=r"(afr[mi][1]), "=r"(afr[mi][2]), "=r"(afr[mi][3])
                             : "r"(addr));
            }
            uint32_t bfr[4][2];
#pragma unroll
            for (int np = 0; np < 2; ++np) {
                int r  = warpN * 32 + np * 16 + (lane & 15);
                int ch = ks * 2 + (lane >> 4);
                uint32_t addr = smem_u32(&Bs[buf][r * LDS + ch * 8]);
                uint32_t r0, r1, r2, r3;
                asm volatile("ldmatrix.sync.aligned.m8n8.x4.shared.b16 {%0,%1,%2,%3}, [%4];"
                             : "=r"(r0), "=r"(r1), "=r"(r2), "=r"(r3)
                             : "r"(addr));
                bfr[np * 2][0] = r0; bfr[np * 2 + 1][0] = r1;
                bfr[np * 2][1] = r2; bfr[np * 2 + 1][1] = r3;
            }
#pragma unroll
            for (int mi = 0; mi < 4; ++mi)
#pragma unroll
                for (int ni = 0; ni < 4; ++ni) {
                    asm volatile(
                        "mma.sync.aligned.m16n8k16.row.col.f32.f16.f16.f32 "
                        "{%0,%1,%2,%3}, {%4,%5,%6,%7}, {%8,%9}, {%0,%1,%2,%3};"
                        : "+f"(acc[mi][ni][0]), "+f"(acc[mi][ni][1]),
                          "+f"(acc[mi][ni][2]), "+f"(acc[mi][ni][3])
                        : "r"(afr[mi][0]), "r"(afr[mi][1]), "r"(afr[mi][2]), "r"(afr[mi][3]),
                          "r"(bfr[ni][0]), "r"(bfr[ni][1]));
                }
        }
        __syncthreads();
    }

    float* Ldst = g_lev[ks_id];
    int rbase = bm * BM + warpM * 64;
#pragma unroll
    for (int mi = 0; mi < 4; mi++) {
        int r0 = rbase + mi * 16 + (lane >> 2);
#pragma unroll
        for (int ni = 0; ni < 4; ni++) {
            int c0 = warpN * 32 + ni * 8 + (lane & 3) * 2;
            Ldst[(size_t)r0 * NLEV + c0]           = acc[mi][ni][0];
            Ldst[(size_t)r0 * NLEV + c0 + 1]       = acc[mi][ni][1];
            Ldst[(size_t)(r0 + 8) * NLEV + c0]     = acc[mi][ni][2];
            Ldst[(size_t)(r0 + 8) * NLEV + c0 + 1] = acc[mi][ni][3];
        }
    }
}

// -------- per-row: sum split-K partials, softmax + cumsum over 64 levels --------
__global__ void level_kernel() {
    int row  = blockIdx.x * 8 + (threadIdx.x >> 5);
    int lane = threadIdx.x & 31;
    float xi0 = 0.f, xi1 = 0.f, xf0 = 0.f, xf1 = 0.f;
#pragma unroll
    for (int s = 0; s < KSPLIT; s++) {
        const float* L = g_lev[s] + (size_t)row * NLEV;
        xi0 += L[lane];      xi1 += L[32 + lane];
        xf0 += L[64 + lane]; xf1 += L[96 + lane];
    }

    // ---- i_h = forward inclusive cumsum of softmax(cc_f_h) ----
    float m = fmaxf(xf0, xf1);
#pragma unroll
    for (int o = 16; o; o >>= 1) m = fmaxf(m, __shfl_xor_sync(~0u, m, o));
    float e0 = __expf(xf0 - m), e1 = __expf(xf1 - m);
    float s = e0 + e1;
#pragma unroll
    for (int o = 16; o; o >>= 1) s += __shfl_xor_sync(~0u, s, o);
    float inv = 1.0f / s;
    float s0 = e0;
#pragma unroll
    for (int o = 1; o < 32; o <<= 1) { float v = __shfl_up_sync(~0u, s0, o); if (lane >= o) s0 += v; }
    float tot0 = __shfl_sync(~0u, s0, 31);
    float s1 = e1;
#pragma unroll
    for (int o = 1; o < 32; o <<= 1) { float v = __shfl_up_sync(~0u, s1, o); if (lane >= o) s1 += v; }
    g_ih[(size_t)row * LVL + lane]      = s0 * inv;
    g_ih[(size_t)row * LVL + 32 + lane] = (tot0 + s1) * inv;

    // ---- f_h = reverse inclusive cumsum of softmax(cc_i_h) ----
    float mq = fmaxf(xi0, xi1);
#pragma unroll
    for (int o = 16; o; o >>= 1) mq = fmaxf(mq, __shfl_xor_sync(~0u, mq, o));
    float q0 = __expf(xi0 - mq), q1 = __expf(xi1 - mq);
    float sq = q0 + q1;
#pragma unroll
    for (int o = 16; o; o >>= 1) sq += __shfl_xor_sync(~0u, sq, o);
    float invq = 1.0f / sq;
    float r1 = q1;
#pragma unroll
    for (int o = 1; o < 32; o <<= 1) { float v = __shfl_down_sync(~0u, r1, o); if (lane < 32 - o) r1 += v; }
    float tot1 = __shfl_sync(~0u, r1, 0);
    float r0 = q0;
#pragma unroll
    for (int o = 1; o < 32; o <<= 1) { float v = __shfl_down_sync(~0u, r0, o); if (lane < 32 - o) r0 += v; }
    g_fh[(size_t)row * LVL + lane]      = (r0 + tot1) * invq;
    g_fh[(size_t)row * LVL + 32 + lane] = r1 * invq;
}

extern "C" void kernel_launch(void* const* d_in, const int* in_sizes, int n_in,
                              void* d_out, int out_size) {
    const float* input   = (const float*)d_in[0];
    const float* h_prev  = (const float*)d_in[1];
    const float* c_prev  = (const float*)d_in[2];
    const float* W_lstm  = (const float*)d_in[3];
    const float* W_level = (const float*)d_in[4];
    float* out = (float*)d_out;

    const int smem_main = 3 * STG * 2 * 2;   // 3 stages x (A+B) x 5120 halves = 61440 B
    cudaFuncSetAttribute(gemm_main, cudaFuncAttributeMaxDynamicSharedMemorySize, smem_main);

    const int prep_blocks = (A4CNT + W4CNT + 255) / 256;
    prep_all<<<prep_blocks, 256>>>(input, h_prev, W_lstm, W_level);        // launch 0
    gemm_level<<<dim3(KSPLIT, BSZ / 128), 256>>>();                        // launch 1
    level_kernel<<<BSZ / 8, 256>>>();                                      // launch 2
    gemm_main<<<dim3(NGATE / BN, BSZ / BM), 256, smem_main>>>(c_prev, out); // launch 3 (ncu slot)
}

// round 13
// speedup vs baseline: 1.2378x; 1.0150x over previous
#include <cuda_runtime.h>
#include <cuda_fp16.h>
#include <cstdint>

#define BSZ   8192
#define HID   1024
#define KDIM  2048
#define LVL   64
#define NGATE 4096
#define NLEV  128
#define KSPLIT 4

// -------- scratch (static __device__, no allocations) --------
__device__ __half g_A[(size_t)BSZ * KDIM];            // fp16 combined input
__device__ __half g_W[(size_t)(NGATE + NLEV) * KDIM]; // fp16 reordered weights
__device__ float  g_lev[KSPLIT][(size_t)BSZ * NLEV];  // level logit partials (split-K)
__device__ float  g_ih[(size_t)BSZ * LVL];
__device__ float  g_fh[(size_t)BSZ * LVL];

__device__ __forceinline__ float sigmoidf_(float x) { return 1.0f / (1.0f + __expf(-x)); }
__device__ __forceinline__ uint32_t smem_u32(const void* p) {
    return (uint32_t)__cvta_generic_to_shared(p);
}

// -------- merged prep: fp32 -> fp16 for A (combined) and W (gate-interleaved) --------
#define A4CNT (BSZ * 512)                      // float4 chunks in A
#define W4CNT ((NGATE + NLEV) * 512)           // float4 chunks in W
__global__ void prep_all(const float* __restrict__ inp, const float* __restrict__ hprev,
                         const float* __restrict__ wl, const float* __restrict__ wv) {
    int idx = blockIdx.x * blockDim.x + threadIdx.x;
    if (idx < A4CNT) {
        int row = idx >> 9;
        int c4  = idx & 511;
        const float* src = (c4 < 256) ? (inp + (size_t)row * 1024 + c4 * 4)
                                      : (hprev + (size_t)row * 1024 + (c4 - 256) * 4);
        float4 v = *reinterpret_cast<const float4*>(src);
        __half2* dst = reinterpret_cast<__half2*>(g_A + (size_t)row * KDIM + c4 * 4);
        dst[0] = __floats2half2_rn(v.x, v.y);
        dst[1] = __floats2half2_rn(v.z, v.w);
    } else if (idx < A4CNT + W4CNT) {
        int j  = idx - A4CNT;
        int n  = j >> 9;
        int c4 = j & 511;
        const float* src;
        if (n < NGATE) src = wl + (size_t)((n & 3) * 1024 + (n >> 2)) * KDIM + c4 * 4;
        else           src = wv + (size_t)(n - NGATE) * KDIM + c4 * 4;
        float4 v = *reinterpret_cast<const float4*>(src);
        __half2* dst = reinterpret_cast<__half2*>(g_W + (size_t)n * KDIM + c4 * 4);
        dst[0] = __floats2half2_rn(v.x, v.y);
        dst[1] = __floats2half2_rn(v.z, v.w);
    }
}

#define BM 128
#define BN 128
#define BK 32
#define LDS 40        // padded half stride (80B) -> conflict-free ldmatrix
#define STG 5120      // halves per stage per operand (128*40)
#define STG2 (STG*2)  // bytes per stage per operand

// ================= main GEMM: 128x128, 3-stage cp.async, hoisted addressing =================
__global__ __launch_bounds__(256, 2) void gemm_main(const float* __restrict__ c_prev,
                                                    float* __restrict__ d_out) {
    extern __shared__ __half sm[];
    __half* Asm = sm;               // 3 stages x STG
    __half* Bsm = sm + 3 * STG;     // 3 stages x STG

    const int tid   = threadIdx.x;
    const int lane  = tid & 31;
    const int wid   = tid >> 5;
    const int warpM = wid >> 2;   // 0..1 (64 rows each)
    const int warpN = wid & 3;    // 0..3 (32 cols each)
    const int bm    = blockIdx.y;
    const int bn    = blockIdx.x;

    const __half* Ag = g_A + (size_t)(bm * BM) * KDIM;
    const __half* Bg = g_W + (size_t)(bn * BN) * KDIM;

    float acc[4][4][4];
#pragma unroll
    for (int a = 0; a < 4; a++)
#pragma unroll
        for (int b = 0; b < 4; b++)
#pragma unroll
            for (int c = 0; c < 4; c++) acc[a][b][c] = 0.0f;

    const int KT = KDIM / BK;  // 64

    // ---- hoisted ldmatrix addresses (stage 0; rotate with coff) ----
    uint32_t aAd[2][4], bAd[2][2];
    {
        const int lr = lane & 15, lc = lane >> 4;
#pragma unroll
        for (int ks = 0; ks < 2; ++ks) {
            const int ch = ks * 2 + lc;
#pragma unroll
            for (int mi = 0; mi < 4; ++mi)
                aAd[ks][mi] = smem_u32(Asm + (warpM * 64 + mi * 16 + lr) * LDS + ch * 8);
#pragma unroll
            for (int np = 0; np < 2; ++np)
                bAd[ks][np] = smem_u32(Bsm + (warpN * 32 + np * 16 + lr) * LDS + ch * 8);
        }
    }

    // ---- hoisted cp.async addressing (stage 0 dsts; rotate with loff; srcs bump by BK) ----
    const int lrow = tid >> 2, lch = tid & 3;
    const uint32_t dA0 = smem_u32(Asm + lrow * LDS + lch * 8);
    const uint32_t dA1 = smem_u32(Asm + (lrow + 64) * LDS + lch * 8);
    const uint32_t dB0 = dA0 + 3 * STG2;
    const uint32_t dB1 = dA1 + 3 * STG2;
    const __half* pA0 = Ag + (size_t)lrow * KDIM + lch * 8;
    const __half* pA1 = Ag + (size_t)(lrow + 64) * KDIM + lch * 8;
    const __half* pB0 = Bg + (size_t)lrow * KDIM + lch * 8;
    const __half* pB1 = Bg + (size_t)(lrow + 64) * KDIM + lch * 8;

    auto load_stage = [&](uint32_t off) {
        asm volatile("cp.async.cg.shared.global [%0], [%1], 16;\n" ::"r"(dA0 + off), "l"(pA0));
        asm volatile("cp.async.cg.shared.global [%0], [%1], 16;\n" ::"r"(dA1 + off), "l"(pA1));
        asm volatile("cp.async.cg.shared.global [%0], [%1], 16;\n" ::"r"(dB0 + off), "l"(pB0));
        asm volatile("cp.async.cg.shared.global [%0], [%1], 16;\n" ::"r"(dB1 + off), "l"(pB1));
        asm volatile("cp.async.commit_group;\n");
        pA0 += BK; pA1 += BK; pB0 += BK; pB1 += BK;
    };

    load_stage(0);
    load_stage(STG2);

    uint32_t coff = 0;            // compute-stage byte offset
    uint32_t loff = 2 * STG2;     // load-stage byte offset

#pragma unroll 1
    for (int kt = 0; kt < KT; ++kt) {
        if (kt == KT - 1) asm volatile("cp.async.wait_group 0;\n");
        else              asm volatile("cp.async.wait_group 1;\n");
        __syncthreads();
        if (kt + 2 < KT) {
            load_stage(loff);
            loff = (loff == 2 * STG2) ? 0u : loff + STG2;
        }

#pragma unroll
        for (int ks = 0; ks < 2; ++ks) {
            uint32_t afr[4][4];
#pragma unroll
            for (int mi = 0; mi < 4; ++mi)
                asm volatile("ldmatrix.sync.aligned.m8n8.x4.shared.b16 {%0,%1,%2,%3}, [%4];"
                             : "=r"(afr[mi][0]), "=r"(afr[mi][1]), "=r"(afr[mi][2]), "=r"(afr[mi][3])
                             : "r"(aAd[ks][mi] + coff));
            uint32_t bfr[4][2];
#pragma unroll
            for (int np = 0; np < 2; ++np) {
                uint32_t r0, r1, r2, r3;
                asm volatile("ldmatrix.sync.aligned.m8n8.x4.shared.b16 {%0,%1,%2,%3}, [%4];"
                             : "=r"(r0), "=r"(r1), "=r"(r2), "=r"(r3)
                             : "r"(bAd[ks][np] + coff));
                bfr[np * 2][0] = r0; bfr[np * 2 + 1][0] = r1;
                bfr[np * 2][1] = r2; bfr[np * 2 + 1][1] = r3;
            }
#pragma unroll
            for (int mi = 0; mi < 4; ++mi)
#pragma unroll
                for (int ni = 0; ni < 4; ++ni) {
                    asm volatile(
                        "mma.sync.aligned.m16n8k16.row.col.f32.f16.f16.f32 "
                        "{%0,%1,%2,%3}, {%4,%5,%6,%7}, {%8,%9}, {%0,%1,%2,%3};"
                        : "+f"(acc[mi][ni][0]), "+f"(acc[mi][ni][1]),
                          "+f"(acc[mi][ni][2]), "+f"(acc[mi][ni][3])
                        : "r"(afr[mi][0]), "r"(afr[mi][1]), "r"(afr[mi][2]), "r"(afr[mi][3]),
                          "r"(bfr[ni][0]), "r"(bfr[ni][1]));
                }
        }
        coff = (coff == 2 * STG2) ? 0u : coff + STG2;
    }

    // Fused ON-LSTM epilogue. Columns gate-interleaved: col -> (j = col>>2, gate = col&3).
    const int lane4 = lane & 3;
    const bool evenl = (lane4 & 1) == 0;
    float* outH = d_out;
    float* outC = d_out + (size_t)BSZ * HID;
    int rbase = bm * BM + warpM * 64;
#pragma unroll
    for (int mi = 0; mi < 4; mi++) {
        int r0 = rbase + mi * 16 + (lane >> 2);
#pragma unroll
        for (int ni = 0; ni < 4; ni++) {
            float p0 = __shfl_xor_sync(0xffffffffu, acc[mi][ni][0], 1);
            float p1 = __shfl_xor_sync(0xffffffffu, acc[mi][ni][1], 1);
            float p2 = __shfl_xor_sync(0xffffffffu, acc[mi][ni][2], 1);
            float p3 = __shfl_xor_sync(0xffffffffu, acc[mi][ni][3], 1);
            if (evenl) {
                int j  = (bn * BN + warpN * 32 + ni * 8 + lane4 * 2) >> 2;
                int lv = j >> 4;
                {
                    float iv = sigmoidf_(acc[mi][ni][0]);
                    float fv = sigmoidf_(acc[mi][ni][1]);
                    float ov = sigmoidf_(p0);
                    float gv = tanhf(p1);
                    float cp = c_prev[(size_t)r0 * HID + j];
                    float ih = g_ih[(size_t)r0 * LVL + lv];
                    float fh = g_fh[(size_t)r0 * LVL + lv];
                    float w  = ih * fh;
                    float cn = w * (fv * cp + iv * gv) + (fh - w) * cp + (ih - w) * gv;
                    outC[(size_t)r0 * HID + j] = cn;
                    outH[(size_t)r0 * HID + j] = ov * tanhf(cn);
                }
                {
                    int r1 = r0 + 8;
                    float iv = sigmoidf_(acc[mi][ni][2]);
                    float fv = sigmoidf_(acc[mi][ni][3]);
                    float ov = sigmoidf_(p2);
                    float gv = tanhf(p3);
                    float cp = c_prev[(size_t)r1 * HID + j];
                    float ih = g_ih[(size_t)r1 * LVL + lv];
                    float fh = g_fh[(size_t)r1 * LVL + lv];
                    float w  = ih * fh;
                    float cn = w * (fv * cp + iv * gv) + (fh - w) * cp + (ih - w) * gv;
                    outC[(size_t)r1 * HID + j] = cn;
                    outH[(size_t)r1 * HID + j] = ov * tanhf(cn);
                }
            }
        }
    }
}

// ================= level GEMM: 128x128 tile, split-K over 4 slices (unchanged) =================
__global__ __launch_bounds__(256, 2) void gemm_level(void) {
    __shared__ __half As[2][BM * LDS];
    __shared__ __half Bs[2][BM * LDS];
    const int tid   = threadIdx.x;
    const int lane  = tid & 31;
    const int wid   = tid >> 5;
    const int warpM = wid >> 2;
    const int warpN = wid & 3;
    const int bm    = blockIdx.y;
    const int ks_id = blockIdx.x;             // K split 0..3
    const int kbase = ks_id * (KDIM / KSPLIT);

    const __half* Ag = g_A + (size_t)(bm * BM) * KDIM + kbase;
    const __half* Bg = g_W + (size_t)NGATE * KDIM + kbase;

    float acc[4][4][4];
#pragma unroll
    for (int a = 0; a < 4; a++)
#pragma unroll
        for (int b = 0; b < 4; b++)
#pragma unroll
            for (int c = 0; c < 4; c++) acc[a][b][c] = 0.0f;

    const int KT = (KDIM / KSPLIT) / BK;  // 16

    auto load_tile = [&](int buf, int kt) {
        int k0 = kt * BK;
#pragma unroll
        for (int i = 0; i < 2; i++) {
            int lin = tid + i * 256;
            int row = lin >> 2, ch = lin & 3;
            uint32_t da = smem_u32(&As[buf][row * LDS + ch * 8]);
            const __half* sa = Ag + (size_t)row * KDIM + k0 + ch * 8;
            asm volatile("cp.async.cg.shared.global [%0], [%1], 16;\n" ::"r"(da), "l"(sa));
            uint32_t db = smem_u32(&Bs[buf][row * LDS + ch * 8]);
            const __half* sb = Bg + (size_t)row * KDIM + k0 + ch * 8;
            asm volatile("cp.async.cg.shared.global [%0], [%1], 16;\n" ::"r"(db), "l"(sb));
        }
        asm volatile("cp.async.commit_group;\n");
    };

    load_tile(0, 0);
#pragma unroll 1
    for (int kt = 0; kt < KT; ++kt) {
        int buf = kt & 1;
        if (kt + 1 < KT) {
            load_tile(buf ^ 1, kt + 1);
            asm volatile("cp.async.wait_group 1;\n");
        } else {
            asm volatile("cp.async.wait_group 0;\n");
        }
        __syncthreads();
#pragma unroll
        for (int ks = 0; ks < 2; ++ks) {
            uint32_t afr[4][4];
#pragma unroll
            for (int mi = 0; mi < 4; ++mi) {
                int r  = warpM * 64 + mi * 16 + (lane & 15);
                int ch = ks * 2 + (lane >> 4);
                uint32_t addr = smem_u32(&As[buf][r * LDS + ch * 8]);
                asm volatile("ldmatrix.sync.aligned.m8n8.x4.shared.b16 {%0,%1,%2,%3}, [%4];"
                             : "=r"(afr[mi][0]), "=r"(afr[mi][1]), "=r"(afr[mi][2]), "=r"(afr[mi][3])
                             : "r"(addr));
            }
            uint32_t bfr[4][2];
#pragma unroll
            for (int np = 0; np < 2; ++np) {
                int r  = warpN * 32 + np * 16 + (lane & 15);
                int ch = ks * 2 + (lane >> 4);
                uint32_t addr = smem_u32(&Bs[buf][r * LDS + ch * 8]);
                uint32_t r0, r1, r2, r3;
                asm volatile("ldmatrix.sync.aligned.m8n8.x4.shared.b16 {%0,%1,%2,%3}, [%4];"
                             : "=r"(r0), "=r"(r1), "=r"(r2), "=r"(r3)
                             : "r"(addr));
                bfr[np * 2][0] = r0; bfr[np * 2 + 1][0] = r1;
                bfr[np * 2][1] = r2; bfr[np * 2 + 1][1] = r3;
            }
#pragma unroll
            for (int mi = 0; mi < 4; ++mi)
#pragma unroll
                for (int ni = 0; ni < 4; ++ni) {
                    asm volatile(
                        "mma.sync.aligned.m16n8k16.row.col.f32.f16.f16.f32 "
                        "{%0,%1,%2,%3}, {%4,%5,%6,%7}, {%8,%9}, {%0,%1,%2,%3};"
                        : "+f"(acc[mi][ni][0]), "+f"(acc[mi][ni][1]),
                          "+f"(acc[mi][ni][2]), "+f"(acc[mi][ni][3])
                        : "r"(afr[mi][0]), "r"(afr[mi][1]), "r"(afr[mi][2]), "r"(afr[mi][3]),
                          "r"(bfr[ni][0]), "r"(bfr[ni][1]));
                }
        }
        __syncthreads();
    }

    float* Ldst = g_lev[ks_id];
    int rbase = bm * BM + warpM * 64;
#pragma unroll
    for (int mi = 0; mi < 4; mi++) {
        int r0 = rbase + mi * 16 + (lane >> 2);
#pragma unroll
        for (int ni = 0; ni < 4; ni++) {
            int c0 = warpN * 32 + ni * 8 + (lane & 3) * 2;
            Ldst[(size_t)r0 * NLEV + c0]           = acc[mi][ni][0];
            Ldst[(size_t)r0 * NLEV + c0 + 1]       = acc[mi][ni][1];
            Ldst[(size_t)(r0 + 8) * NLEV + c0]     = acc[mi][ni][2];
            Ldst[(size_t)(r0 + 8) * NLEV + c0 + 1] = acc[mi][ni][3];
        }
    }
}

// -------- per-row: sum split-K partials, softmax + cumsum over 64 levels --------
__global__ void level_kernel() {
    int row  = blockIdx.x * 8 + (threadIdx.x >> 5);
    int lane = threadIdx.x & 31;
    float xi0 = 0.f, xi1 = 0.f, xf0 = 0.f, xf1 = 0.f;
#pragma unroll
    for (int s = 0; s < KSPLIT; s++) {
        const float* L = g_lev[s] + (size_t)row * NLEV;
        xi0 += L[lane];      xi1 += L[32 + lane];
        xf0 += L[64 + lane]; xf1 += L[96 + lane];
    }

    // ---- i_h = forward inclusive cumsum of softmax(cc_f_h) ----
    float m = fmaxf(xf0, xf1);
#pragma unroll
    for (int o = 16; o; o >>= 1) m = fmaxf(m, __shfl_xor_sync(~0u, m, o));
    float e0 = __expf(xf0 - m), e1 = __expf(xf1 - m);
    float s = e0 + e1;
#pragma unroll
    for (int o = 16; o; o >>= 1) s += __shfl_xor_sync(~0u, s, o);
    float inv = 1.0f / s;
    float s0 = e0;
#pragma unroll
    for (int o = 1; o < 32; o <<= 1) { float v = __shfl_up_sync(~0u, s0, o); if (lane >= o) s0 += v; }
    float tot0 = __shfl_sync(~0u, s0, 31);
    float s1 = e1;
#pragma unroll
    for (int o = 1; o < 32; o <<= 1) { float v = __shfl_up_sync(~0u, s1, o); if (lane >= o) s1 += v; }
    g_ih[(size_t)row * LVL + lane]      = s0 * inv;
    g_ih[(size_t)row * LVL + 32 + lane] = (tot0 + s1) * inv;

    // ---- f_h = reverse inclusive cumsum of softmax(cc_i_h) ----
    float mq = fmaxf(xi0, xi1);
#pragma unroll
    for (int o = 16; o; o >>= 1) mq = fmaxf(mq, __shfl_xor_sync(~0u, mq, o));
    float q0 = __expf(xi0 - mq), q1 = __expf(xi1 - mq);
    float sq = q0 + q1;
#pragma unroll
    for (int o = 16; o; o >>= 1) sq += __shfl_xor_sync(~0u, sq, o);
    float invq = 1.0f / sq;
    float r1 = q1;
#pragma unroll
    for (int o = 1; o < 32; o <<= 1) { float v = __shfl_down_sync(~0u, r1, o); if (lane < 32 - o) r1 += v; }
    float tot1 = __shfl_sync(~0u, r1, 0);
    float r0 = q0;
#pragma unroll
    for (int o = 1; o < 32; o <<= 1) { float v = __shfl_down_sync(~0u, r0, o); if (lane < 32 - o) r0 += v; }
    g_fh[(size_t)row * LVL + lane]      = (r0 + tot1) * invq;
    g_fh[(size_t)row * LVL + 32 + lane] = r1 * invq;
}

extern "C" void kernel_launch(void* const* d_in, const int* in_sizes, int n_in,
                              void* d_out, int out_size) {
    const float* input   = (const float*)d_in[0];
    const float* h_prev  = (const float*)d_in[1];
    const float* c_prev  = (const float*)d_in[2];
    const float* W_lstm  = (const float*)d_in[3];
    const float* W_level = (const float*)d_in[4];
    float* out = (float*)d_out;

    const int smem_main = 3 * STG2 * 2;   // 3 stages x (A+B) = 61440 B
    cudaFuncSetAttribute(gemm_main, cudaFuncAttributeMaxDynamicSharedMemorySize, smem_main);

    const int prep_blocks = (A4CNT + W4CNT + 255) / 256;
    prep_all<<<prep_blocks, 256>>>(input, h_prev, W_lstm, W_level);        // launch 0
    gemm_level<<<dim3(KSPLIT, BSZ / 128), 256>>>();                        // launch 1
    level_kernel<<<BSZ / 8, 256>>>();                                      // launch 2
    gemm_main<<<dim3(NGATE / BN, BSZ / BM), 256, smem_main>>>(c_prev, out); // launch 3 (ncu slot)
}

// round 14
// speedup vs baseline: 1.3632x; 1.1012x over previous
#include <cuda_runtime.h>
#include <cuda_fp16.h>
#include <cstdint>

#define BSZ   8192
#define HID   1024
#define KDIM  2048
#define LVL   64
#define NGATE 4096
#define NLEV  128
#define KSPLIT 4

// -------- scratch (static __device__, no allocations) --------
__device__ __half g_A[(size_t)BSZ * KDIM];            // fp16 combined input
__device__ __half g_W[(size_t)(NGATE + NLEV) * KDIM]; // fp16 reordered weights
__device__ float  g_lev[KSPLIT][(size_t)BSZ * NLEV];  // level logit partials (split-K)
__device__ float  g_ih[(size_t)BSZ * LVL];
__device__ float  g_fh[(size_t)BSZ * LVL];

__device__ __forceinline__ float sigmoidf_(float x) { return 1.0f / (1.0f + __expf(-x)); }
__device__ __forceinline__ uint32_t smem_u32(const void* p) {
    return (uint32_t)__cvta_generic_to_shared(p);
}

// -------- merged prep: fp32 -> fp16 for A (combined) and W (gate-interleaved) --------
#define A4CNT (BSZ * 512)                      // float4 chunks in A
#define W4CNT ((NGATE + NLEV) * 512)           // float4 chunks in W
__global__ void prep_all(const float* __restrict__ inp, const float* __restrict__ hprev,
                         const float* __restrict__ wl, const float* __restrict__ wv) {
    int idx = blockIdx.x * blockDim.x + threadIdx.x;
    if (idx < A4CNT) {
        int row = idx >> 9;
        int c4  = idx & 511;
        const float* src = (c4 < 256) ? (inp + (size_t)row * 1024 + c4 * 4)
                                      : (hprev + (size_t)row * 1024 + (c4 - 256) * 4);
        float4 v = *reinterpret_cast<const float4*>(src);
        __half2* dst = reinterpret_cast<__half2*>(g_A + (size_t)row * KDIM + c4 * 4);
        dst[0] = __floats2half2_rn(v.x, v.y);
        dst[1] = __floats2half2_rn(v.z, v.w);
    } else if (idx < A4CNT + W4CNT) {
        int j  = idx - A4CNT;
        int n  = j >> 9;
        int c4 = j & 511;
        const float* src;
        if (n < NGATE) src = wl + (size_t)((n & 3) * 1024 + (n >> 2)) * KDIM + c4 * 4;
        else           src = wv + (size_t)(n - NGATE) * KDIM + c4 * 4;
        float4 v = *reinterpret_cast<const float4*>(src);
        __half2* dst = reinterpret_cast<__half2*>(g_W + (size_t)n * KDIM + c4 * 4);
        dst[0] = __floats2half2_rn(v.x, v.y);
        dst[1] = __floats2half2_rn(v.z, v.w);
    }
}

#define BM 128
#define BN 128

// ---- main-GEMM pipeline geometry (BK=64, 3 stages) ----
#define BKM   64
#define LDSK  72                   // padded half stride (144B rows) -> conflict-free ldmatrix
#define MSTG  (128 * LDSK)         // halves per stage per operand (9216)
#define MSTG2 (MSTG * 2)           // bytes per stage per operand (18432)

// ================= main GEMM: 128x128, BK=64, 3-stage cp.async, 1 sync/iter =================
__global__ __launch_bounds__(256, 2) void gemm_main(const float* __restrict__ c_prev,
                                                    float* __restrict__ d_out) {
    extern __shared__ __half sm[];
    __half* Asm = sm;                // 3 stages x MSTG
    __half* Bsm = sm + 3 * MSTG;     // 3 stages x MSTG

    const int tid   = threadIdx.x;
    const int lane  = tid & 31;
    const int wid   = tid >> 5;
    const int warpM = wid >> 2;   // 0..1 (64 rows each)
    const int warpN = wid & 3;    // 0..3 (32 cols each)
    const int bm    = blockIdx.y;
    const int bn    = blockIdx.x;

    const __half* Ag = g_A + (size_t)(bm * BM) * KDIM;
    const __half* Bg = g_W + (size_t)(bn * BN) * KDIM;

    float acc[4][4][4];
#pragma unroll
    for (int a = 0; a < 4; a++)
#pragma unroll
        for (int b = 0; b < 4; b++)
#pragma unroll
            for (int c = 0; c < 4; c++) acc[a][b][c] = 0.0f;

    const int KT = KDIM / BKM;  // 32

    // ---- hoisted ldmatrix base addresses (ks=0 chunk; +ks*32B per ks, +coff per stage) ----
    uint32_t aAd[4], bAd[2];
    {
        const int lr = lane & 15, lc = lane >> 4;
#pragma unroll
        for (int mi = 0; mi < 4; ++mi)
            aAd[mi] = smem_u32(Asm + (warpM * 64 + mi * 16 + lr) * LDSK + lc * 8);
#pragma unroll
        for (int np = 0; np < 2; ++np)
            bAd[np] = smem_u32(Bsm + (warpN * 32 + np * 16 + lr) * LDSK + lc * 8);
    }

    // ---- hoisted cp.async addressing: thread loads 4 A rows + 4 B rows (8 chunks of 16B) ----
    const int lrow = tid >> 3, lch = tid & 7;   // 32 rows x 8 chunks per 256-thread pass
    const uint32_t dA0 = smem_u32(Asm + lrow * LDSK + lch * 8);
    const uint32_t dB0 = dA0 + 3 * MSTG2;
    const __half* pA0 = Ag + (size_t)lrow * KDIM + lch * 8;
    const __half* pB0 = Bg + (size_t)lrow * KDIM + lch * 8;

    auto load_stage = [&](uint32_t off) {
#pragma unroll
        for (int i = 0; i < 4; i++) {
            asm volatile("cp.async.cg.shared.global [%0], [%1], 16;\n"
                         ::"r"(dA0 + off + i * (32 * LDSK * 2)), "l"(pA0 + (size_t)i * 32 * KDIM));
            asm volatile("cp.async.cg.shared.global [%0], [%1], 16;\n"
                         ::"r"(dB0 + off + i * (32 * LDSK * 2)), "l"(pB0 + (size_t)i * 32 * KDIM));
        }
        asm volatile("cp.async.commit_group;\n");
        pA0 += BKM; pB0 += BKM;
    };

    load_stage(0);
    load_stage(MSTG2);

    uint32_t coff = 0;            // compute-stage byte offset
    uint32_t loff = 2 * MSTG2;    // load-stage byte offset

#pragma unroll 1
    for (int kt = 0; kt < KT; ++kt) {
        if (kt == KT - 1) asm volatile("cp.async.wait_group 0;\n");
        else              asm volatile("cp.async.wait_group 1;\n");
        __syncthreads();
        if (kt + 2 < KT) {
            load_stage(loff);
            loff = (loff == 2 * MSTG2) ? 0u : loff + MSTG2;
        }

#pragma unroll
        for (int ks = 0; ks < 4; ++ks) {
            const uint32_t kso = coff + ks * 32;   // ks*2 chunks of 16B
            uint32_t afr[4][4];
#pragma unroll
            for (int mi = 0; mi < 4; ++mi)
                asm volatile("ldmatrix.sync.aligned.m8n8.x4.shared.b16 {%0,%1,%2,%3}, [%4];"
                             : "=r"(afr[mi][0]), "=r"(afr[mi][1]), "=r"(afr[mi][2]), "=r"(afr[mi][3])
                             : "r"(aAd[mi] + kso));
            uint32_t bfr[4][2];
#pragma unroll
            for (int np = 0; np < 2; ++np) {
                uint32_t r0, r1, r2, r3;
                asm volatile("ldmatrix.sync.aligned.m8n8.x4.shared.b16 {%0,%1,%2,%3}, [%4];"
                             : "=r"(r0), "=r"(r1), "=r"(r2), "=r"(r3)
                             : "r"(bAd[np] + kso));
                bfr[np * 2][0] = r0; bfr[np * 2 + 1][0] = r1;
                bfr[np * 2][1] = r2; bfr[np * 2 + 1][1] = r3;
            }
#pragma unroll
            for (int mi = 0; mi < 4; ++mi)
#pragma unroll
                for (int ni = 0; ni < 4; ++ni) {
                    asm volatile(
                        "mma.sync.aligned.m16n8k16.row.col.f32.f16.f16.f32 "
                        "{%0,%1,%2,%3}, {%4,%5,%6,%7}, {%8,%9}, {%0,%1,%2,%3};"
                        : "+f"(acc[mi][ni][0]), "+f"(acc[mi][ni][1]),
                          "+f"(acc[mi][ni][2]), "+f"(acc[mi][ni][3])
                        : "r"(afr[mi][0]), "r"(afr[mi][1]), "r"(afr[mi][2]), "r"(afr[mi][3]),
                          "r"(bfr[ni][0]), "r"(bfr[ni][1]));
                }
        }
        coff = (coff == 2 * MSTG2) ? 0u : coff + MSTG2;
    }

    // Fused ON-LSTM epilogue. Columns gate-interleaved: col -> (j = col>>2, gate = col&3).
    const int lane4 = lane & 3;
    const bool evenl = (lane4 & 1) == 0;
    float* outH = d_out;
    float* outC = d_out + (size_t)BSZ * HID;
    int rbase = bm * BM + warpM * 64;
#pragma unroll
    for (int mi = 0; mi < 4; mi++) {
        int r0 = rbase + mi * 16 + (lane >> 2);
#pragma unroll
        for (int ni = 0; ni < 4; ni++) {
            float p0 = __shfl_xor_sync(0xffffffffu, acc[mi][ni][0], 1);
            float p1 = __shfl_xor_sync(0xffffffffu, acc[mi][ni][1], 1);
            float p2 = __shfl_xor_sync(0xffffffffu, acc[mi][ni][2], 1);
            float p3 = __shfl_xor_sync(0xffffffffu, acc[mi][ni][3], 1);
            if (evenl) {
                int j  = (bn * BN + warpN * 32 + ni * 8 + lane4 * 2) >> 2;
                int lv = j >> 4;
                {
                    float iv = sigmoidf_(acc[mi][ni][0]);
                    float fv = sigmoidf_(acc[mi][ni][1]);
                    float ov = sigmoidf_(p0);
                    float gv = tanhf(p1);
                    float cp = c_prev[(size_t)r0 * HID + j];
                    float ih = g_ih[(size_t)r0 * LVL + lv];
                    float fh = g_fh[(size_t)r0 * LVL + lv];
                    float w  = ih * fh;
                    float cn = w * (fv * cp + iv * gv) + (fh - w) * cp + (ih - w) * gv;
                    outC[(size_t)r0 * HID + j] = cn;
                    outH[(size_t)r0 * HID + j] = ov * tanhf(cn);
                }
                {
                    int r1 = r0 + 8;
                    float iv = sigmoidf_(acc[mi][ni][2]);
                    float fv = sigmoidf_(acc[mi][ni][3]);
                    float ov = sigmoidf_(p2);
                    float gv = tanhf(p3);
                    float cp = c_prev[(size_t)r1 * HID + j];
                    float ih = g_ih[(size_t)r1 * LVL + lv];
                    float fh = g_fh[(size_t)r1 * LVL + lv];
                    float w  = ih * fh;
                    float cn = w * (fv * cp + iv * gv) + (fh - w) * cp + (ih - w) * gv;
                    outC[(size_t)r1 * HID + j] = cn;
                    outH[(size_t)r1 * HID + j] = ov * tanhf(cn);
                }
            }
        }
    }
}

// ================= level GEMM: 128x128 tile, split-K over 4 slices (unchanged) =================
#define BK 32
#define LDS 40
__global__ __launch_bounds__(256, 2) void gemm_level(void) {
    __shared__ __half As[2][BM * LDS];
    __shared__ __half Bs[2][BM * LDS];
    const int tid   = threadIdx.x;
    const int lane  = tid & 31;
    const int wid   = tid >> 5;
    const int warpM = wid >> 2;
    const int warpN = wid & 3;
    const int bm    = blockIdx.y;
    const int ks_id = blockIdx.x;             // K split 0..3
    const int kbase = ks_id * (KDIM / KSPLIT);

    const __half* Ag = g_A + (size_t)(bm * BM) * KDIM + kbase;
    const __half* Bg = g_W + (size_t)NGATE * KDIM + kbase;

    float acc[4][4][4];
#pragma unroll
    for (int a = 0; a < 4; a++)
#pragma unroll
        for (int b = 0; b < 4; b++)
#pragma unroll
            for (int c = 0; c < 4; c++) acc[a][b][c] = 0.0f;

    const int KT = (KDIM / KSPLIT) / BK;  // 16

    auto load_tile = [&](int buf, int kt) {
        int k0 = kt * BK;
#pragma unroll
        for (int i = 0; i < 2; i++) {
            int lin = tid + i * 256;
            int row = lin >> 2, ch = lin & 3;
            uint32_t da = smem_u32(&As[buf][row * LDS + ch * 8]);
            const __half* sa = Ag + (size_t)row * KDIM + k0 + ch * 8;
            asm volatile("cp.async.cg.shared.global [%0], [%1], 16;\n" ::"r"(da), "l"(sa));
            uint32_t db = smem_u32(&Bs[buf][row * LDS + ch * 8]);
            const __half* sb = Bg + (size_t)row * KDIM + k0 + ch * 8;
            asm volatile("cp.async.cg.shared.global [%0], [%1], 16;\n" ::"r"(db), "l"(sb));
        }
        asm volatile("cp.async.commit_group;\n");
    };

    load_tile(0, 0);
#pragma unroll 1
    for (int kt = 0; kt < KT; ++kt) {
        int buf = kt & 1;
        if (kt + 1 < KT) {
            load_tile(buf ^ 1, kt + 1);
            asm volatile("cp.async.wait_group 1;\n");
        } else {
            asm volatile("cp.async.wait_group 0;\n");
        }
        __syncthreads();
#pragma unroll
        for (int ks = 0; ks < 2; ++ks) {
            uint32_t afr[4][4];
#pragma unroll
            for (int mi = 0; mi < 4; ++mi) {
                int r  = warpM * 64 + mi * 16 + (lane & 15);
                int ch = ks * 2 + (lane >> 4);
                uint32_t addr = smem_u32(&As[buf][r * LDS + ch * 8]);
                asm volatile("ldmatrix.sync.aligned.m8n8.x4.shared.b16 {%0,%1,%2,%3}, [%4];"
                             : "=r"(afr[mi][0]), "=r"(afr[mi][1]), "=r"(afr[mi][2]), "=r"(afr[mi][3])
                             : "r"(addr));
            }
            uint32_t bfr[4][2];
#pragma unroll
            for (int np = 0; np < 2; ++np) {
                int r  = warpN * 32 + np * 16 + (lane & 15);
                int ch = ks * 2 + (lane >> 4);
                uint32_t addr = smem_u32(&Bs[buf][r * LDS + ch * 8]);
                uint32_t r0, r1, r2, r3;
                asm volatile("ldmatrix.sync.aligned.m8n8.x4.shared.b16 {%0,%1,%2,%3}, [%4];"
                             : "=r"(r0), "=r"(r1), "=r"(r2), "=r"(r3)
                             : "r"(addr));
                bfr[np * 2][0] = r0; bfr[np * 2 + 1][0] = r1;
                bfr[np * 2][1] = r2; bfr[np * 2 + 1][1] = r3;
            }
#pragma unroll
            for (int mi = 0; mi < 4; ++mi)
#pragma unroll
                for (int ni = 0; ni < 4; ++ni) {
                    asm volatile(
                        "mma.sync.aligned.m16n8k16.row.col.f32.f16.f16.f32 "
                        "{%0,%1,%2,%3}, {%4,%5,%6,%7}, {%8,%9}, {%0,%1,%2,%3};"
                        : "+f"(acc[mi][ni][0]), "+f"(acc[mi][ni][1]),
                          "+f"(acc[mi][ni][2]), "+f"(acc[mi][ni][3])
                        : "r"(afr[mi][0]), "r"(afr[mi][1]), "r"(afr[mi][2]), "r"(afr[mi][3]),
                          "r"(bfr[ni][0]), "r"(bfr[ni][1]));
                }
        }
        __syncthreads();
    }

    float* Ldst = g_lev[ks_id];
    int rbase = bm * BM + warpM * 64;
#pragma unroll
    for (int mi = 0; mi < 4; mi++) {
        int r0 = rbase + mi * 16 + (lane >> 2);
#pragma unroll
        for (int ni = 0; ni < 4; ni++) {
            int c0 = warpN * 32 + ni * 8 + (lane & 3) * 2;
            Ldst[(size_t)r0 * NLEV + c0]           = acc[mi][ni][0];
            Ldst[(size_t)r0 * NLEV + c0 + 1]       = acc[mi][ni][1];
            Ldst[(size_t)(r0 + 8) * NLEV + c0]     = acc[mi][ni][2];
            Ldst[(size_t)(r0 + 8) * NLEV + c0 + 1] = acc[mi][ni][3];
        }
    }
}

// -------- per-row: sum split-K partials, softmax + cumsum over 64 levels --------
__global__ void level_kernel() {
    int row  = blockIdx.x * 8 + (threadIdx.x >> 5);
    int lane = threadIdx.x & 31;
    float xi0 = 0.f, xi1 = 0.f, xf0 = 0.f, xf1 = 0.f;
#pragma unroll
    for (int s = 0; s < KSPLIT; s++) {
        const float* L = g_lev[s] + (size_t)row * NLEV;
        xi0 += L[lane];      xi1 += L[32 + lane];
        xf0 += L[64 + lane]; xf1 += L[96 + lane];
    }

    // ---- i_h = forward inclusive cumsum of softmax(cc_f_h) ----
    float m = fmaxf(xf0, xf1);
#pragma unroll
    for (int o = 16; o; o >>= 1) m = fmaxf(m, __shfl_xor_sync(~0u, m, o));
    float e0 = __expf(xf0 - m), e1 = __expf(xf1 - m);
    float s = e0 + e1;
#pragma unroll
    for (int o = 16; o; o >>= 1) s += __shfl_xor_sync(~0u, s, o);
    float inv = 1.0f / s;
    float s0 = e0;
#pragma unroll
    for (int o = 1; o < 32; o <<= 1) { float v = __shfl_up_sync(~0u, s0, o); if (lane >= o) s0 += v; }
    float tot0 = __shfl_sync(~0u, s0, 31);
    float s1 = e1;
#pragma unroll
    for (int o = 1; o < 32; o <<= 1) { float v = __shfl_up_sync(~0u, s1, o); if (lane >= o) s1 += v; }
    g_ih[(size_t)row * LVL + lane]      = s0 * inv;
    g_ih[(size_t)row * LVL + 32 + lane] = (tot0 + s1) * inv;

    // ---- f_h = reverse inclusive cumsum of softmax(cc_i_h) ----
    float mq = fmaxf(xi0, xi1);
#pragma unroll
    for (int o = 16; o; o >>= 1) mq = fmaxf(mq, __shfl_xor_sync(~0u, mq, o));
    float q0 = __expf(xi0 - mq), q1 = __expf(xi1 - mq);
    float sq = q0 + q1;
#pragma unroll
    for (int o = 16; o; o >>= 1) sq += __shfl_xor_sync(~0u, sq, o);
    float invq = 1.0f / sq;
    float r1 = q1;
#pragma unroll
    for (int o = 1; o < 32; o <<= 1) { float v = __shfl_down_sync(~0u, r1, o); if (lane < 32 - o) r1 += v; }
    float tot1 = __shfl_sync(~0u, r1, 0);
    float r0 = q0;
#pragma unroll
    for (int o = 1; o < 32; o <<= 1) { float v = __shfl_down_sync(~0u, r0, o); if (lane < 32 - o) r0 += v; }
    g_fh[(size_t)row * LVL + lane]      = (r0 + tot1) * invq;
    g_fh[(size_t)row * LVL + 32 + lane] = r1 * invq;
}

extern "C" void kernel_launch(void* const* d_in, const int* in_sizes, int n_in,
                              void* d_out, int out_size) {
    const float* input   = (const float*)d_in[0];
    const float* h_prev  = (const float*)d_in[1];
    const float* c_prev  = (const float*)d_in[2];
    const float* W_lstm  = (const float*)d_in[3];
    const float* W_level = (const float*)d_in[4];
    float* out = (float*)d_out;

    const int smem_main = 3 * MSTG2 * 2;   // 3 stages x (A+B) x 18432 B = 110592 B
    cudaFuncSetAttribute(gemm_main, cudaFuncAttributeMaxDynamicSharedMemorySize, smem_main);

    const int prep_blocks = (A4CNT + W4CNT + 255) / 256;
    prep_all<<<prep_blocks, 256>>>(input, h_prev, W_lstm, W_level);        // launch 0
    gemm_level<<<dim3(KSPLIT, BSZ / 128), 256>>>();                        // launch 1
    level_kernel<<<BSZ / 8, 256>>>();                                      // launch 2
    gemm_main<<<dim3(NGATE / BN, BSZ / BM), 256, smem_main>>>(c_prev, out); // launch 3 (ncu slot)
}

// round 15
// speedup vs baseline: 1.3710x; 1.0058x over previous
#include <cuda_runtime.h>
#include <cuda_fp16.h>
#include <cstdint>

#define BSZ   8192
#define HID   1024
#define KDIM  2048
#define LVL   64
#define NGATE 4096
#define NLEV  128
#define KSPLIT 4

// -------- scratch (static __device__, no allocations) --------
__device__ __half g_A[(size_t)BSZ * KDIM];            // fp16 combined input
__device__ __half g_W[(size_t)(NGATE + NLEV) * KDIM]; // fp16 reordered weights
__device__ float  g_lev[KSPLIT][(size_t)BSZ * NLEV];  // level logit partials (split-K)
__device__ float  g_ih[(size_t)BSZ * LVL];
__device__ float  g_fh[(size_t)BSZ * LVL];

__device__ __forceinline__ float sigmoidf_(float x) { return 1.0f / (1.0f + __expf(-x)); }
__device__ __forceinline__ uint32_t smem_u32(const void* p) {
    return (uint32_t)__cvta_generic_to_shared(p);
}

// -------- merged prep: fp32 -> fp16 for A (combined) and W (gate-interleaved) --------
#define A4CNT (BSZ * 512)                      // float4 chunks in A
#define W4CNT ((NGATE + NLEV) * 512)           // float4 chunks in W
__global__ void prep_all(const float* __restrict__ inp, const float* __restrict__ hprev,
                         const float* __restrict__ wl, const float* __restrict__ wv) {
    int idx = blockIdx.x * blockDim.x + threadIdx.x;
    if (idx < A4CNT) {
        int row = idx >> 9;
        int c4  = idx & 511;
        const float* src = (c4 < 256) ? (inp + (size_t)row * 1024 + c4 * 4)
                                      : (hprev + (size_t)row * 1024 + (c4 - 256) * 4);
        float4 v = *reinterpret_cast<const float4*>(src);
        __half2* dst = reinterpret_cast<__half2*>(g_A + (size_t)row * KDIM + c4 * 4);
        dst[0] = __floats2half2_rn(v.x, v.y);
        dst[1] = __floats2half2_rn(v.z, v.w);
    } else if (idx < A4CNT + W4CNT) {
        int j  = idx - A4CNT;
        int n  = j >> 9;
        int c4 = j & 511;
        const float* src;
        if (n < NGATE) src = wl + (size_t)((n & 3) * 1024 + (n >> 2)) * KDIM + c4 * 4;
        else           src = wv + (size_t)(n - NGATE) * KDIM + c4 * 4;
        float4 v = *reinterpret_cast<const float4*>(src);
        __half2* dst = reinterpret_cast<__half2*>(g_W + (size_t)n * KDIM + c4 * 4);
        dst[0] = __floats2half2_rn(v.x, v.y);
        dst[1] = __floats2half2_rn(v.z, v.w);
    }
}

#define BM 128
#define BN 128

// ---- main-GEMM pipeline geometry (BK=64, 3 stages) ----
#define BKM   64
#define LDSK  72                   // padded half stride (144B rows) -> conflict-free ldmatrix
#define MSTG  (128 * LDSK)         // halves per stage per operand (9216)
#define MSTG2 (MSTG * 2)           // bytes per stage per operand (18432)
#define AROW  (16 * LDSK * 2)      // 2304 B between 16-row A blocks (compile-time LDSM offsets)

// ================= main GEMM: 128x128, BK=64, 3-stage cp.async, ks-pipelined frags =================
__global__ __launch_bounds__(256, 2) void gemm_main(const float* __restrict__ c_prev,
                                                    float* __restrict__ d_out) {
    extern __shared__ __half sm[];
    __half* Asm = sm;                // 3 stages x MSTG
    __half* Bsm = sm + 3 * MSTG;     // 3 stages x MSTG

    const int tid   = threadIdx.x;
    const int lane  = tid & 31;
    const int wid   = tid >> 5;
    const int warpM = wid >> 2;   // 0..1 (64 rows each)
    const int warpN = wid & 3;    // 0..3 (32 cols each)
    const int bm    = blockIdx.y;
    const int bn    = blockIdx.x;

    const __half* Ag = g_A + (size_t)(bm * BM) * KDIM;
    const __half* Bg = g_W + (size_t)(bn * BN) * KDIM;

    float acc[4][4][4];
#pragma unroll
    for (int a = 0; a < 4; a++)
#pragma unroll
        for (int b = 0; b < 4; b++)
#pragma unroll
            for (int c = 0; c < 4; c++) acc[a][b][c] = 0.0f;

    const int KT = KDIM / BKM;  // 32

    // ---- hoisted ldmatrix base addresses (mi/np deltas are compile-time; folded into LDSM) ----
    uint32_t aBase, bBase;
    {
        const int lr = lane & 15, lc = lane >> 4;
        aBase = smem_u32(Asm + (warpM * 64 + lr) * LDSK + lc * 8);
        bBase = smem_u32(Bsm + (warpN * 32 + lr) * LDSK + lc * 8);
    }

    // ---- hoisted cp.async addressing: thread loads 4 A rows + 4 B rows (16B chunks) ----
    const int lrow = tid >> 3, lch = tid & 7;   // 32 rows x 8 chunks per 256-thread pass
    const uint32_t dA0 = smem_u32(Asm + lrow * LDSK + lch * 8);
    const uint32_t dB0 = dA0 + 3 * MSTG2;
    const __half* pA0 = Ag + (size_t)lrow * KDIM + lch * 8;
    const __half* pB0 = Bg + (size_t)lrow * KDIM + lch * 8;

    auto load_stage = [&](uint32_t off) {
#pragma unroll
        for (int i = 0; i < 4; i++) {
            asm volatile("cp.async.cg.shared.global [%0], [%1], 16;\n"
                         ::"r"(dA0 + off + i * (32 * LDSK * 2)), "l"(pA0 + (size_t)i * 32 * KDIM));
            asm volatile("cp.async.cg.shared.global [%0], [%1], 16;\n"
                         ::"r"(dB0 + off + i * (32 * LDSK * 2)), "l"(pB0 + (size_t)i * 32 * KDIM));
        }
        asm volatile("cp.async.commit_group;\n");
        pA0 += BKM; pB0 += BKM;
    };

    load_stage(0);
    load_stage(MSTG2);

    uint32_t coff = 0;            // compute-stage byte offset
    uint32_t loff = 2 * MSTG2;    // load-stage byte offset

    uint32_t afr[2][4][4];        // ping-pong fragment buffers
    uint32_t bfr[2][4][2];

    auto ld_frag = [&](int buf, uint32_t kso) {
        const uint32_t a0 = aBase + kso;
        const uint32_t b0 = bBase + kso;
#pragma unroll
        for (int mi = 0; mi < 4; ++mi)
            asm volatile("ldmatrix.sync.aligned.m8n8.x4.shared.b16 {%0,%1,%2,%3}, [%4];"
                         : "=r"(afr[buf][mi][0]), "=r"(afr[buf][mi][1]),
                           "=r"(afr[buf][mi][2]), "=r"(afr[buf][mi][3])
                         : "r"(a0 + mi * AROW));
#pragma unroll
        for (int np = 0; np < 2; ++np) {
            uint32_t r0, r1, r2, r3;
            asm volatile("ldmatrix.sync.aligned.m8n8.x4.shared.b16 {%0,%1,%2,%3}, [%4];"
                         : "=r"(r0), "=r"(r1), "=r"(r2), "=r"(r3)
                         : "r"(b0 + np * AROW));
            bfr[buf][np * 2][0] = r0; bfr[buf][np * 2 + 1][0] = r1;
            bfr[buf][np * 2][1] = r2; bfr[buf][np * 2 + 1][1] = r3;
        }
    };

#pragma unroll 1
    for (int kt = 0; kt < KT; ++kt) {
        if (kt == KT - 1) asm volatile("cp.async.wait_group 0;\n");
        else              asm volatile("cp.async.wait_group 1;\n");
        __syncthreads();
        if (kt + 2 < KT) {
            load_stage(loff);
            loff = (loff == 2 * MSTG2) ? 0u : loff + MSTG2;
        }

        ld_frag(0, coff);                      // prologue fragments for ks=0
#pragma unroll
        for (int ks = 0; ks < 4; ++ks) {
            const int cur = ks & 1;
            if (ks < 3) ld_frag(cur ^ 1, coff + (ks + 1) * 32);   // prefetch next ks
#pragma unroll
            for (int mi = 0; mi < 4; ++mi)
#pragma unroll
                for (int ni = 0; ni < 4; ++ni) {
                    asm volatile(
                        "mma.sync.aligned.m16n8k16.row.col.f32.f16.f16.f32 "
                        "{%0,%1,%2,%3}, {%4,%5,%6,%7}, {%8,%9}, {%0,%1,%2,%3};"
                        : "+f"(acc[mi][ni][0]), "+f"(acc[mi][ni][1]),
                          "+f"(acc[mi][ni][2]), "+f"(acc[mi][ni][3])
                        : "r"(afr[cur][mi][0]), "r"(afr[cur][mi][1]),
                          "r"(afr[cur][mi][2]), "r"(afr[cur][mi][3]),
                          "r"(bfr[cur][ni][0]), "r"(bfr[cur][ni][1]));
                }
        }
        coff = (coff == 2 * MSTG2) ? 0u : coff + MSTG2;
    }

    // Fused ON-LSTM epilogue. Columns gate-interleaved: col -> (j = col>>2, gate = col&3).
    const int lane4 = lane & 3;
    const bool evenl = (lane4 & 1) == 0;
    float* outH = d_out;
    float* outC = d_out + (size_t)BSZ * HID;
    int rbase = bm * BM + warpM * 64;
#pragma unroll
    for (int mi = 0; mi < 4; mi++) {
        int r0 = rbase + mi * 16 + (lane >> 2);
#pragma unroll
        for (int ni = 0; ni < 4; ni++) {
            float p0 = __shfl_xor_sync(0xffffffffu, acc[mi][ni][0], 1);
            float p1 = __shfl_xor_sync(0xffffffffu, acc[mi][ni][1], 1);
            float p2 = __shfl_xor_sync(0xffffffffu, acc[mi][ni][2], 1);
            float p3 = __shfl_xor_sync(0xffffffffu, acc[mi][ni][3], 1);
            if (evenl) {
                int j  = (bn * BN + warpN * 32 + ni * 8 + lane4 * 2) >> 2;
                int lv = j >> 4;
                {
                    float iv = sigmoidf_(acc[mi][ni][0]);
                    float fv = sigmoidf_(acc[mi][ni][1]);
                    float ov = sigmoidf_(p0);
                    float gv = tanhf(p1);
                    float cp = c_prev[(size_t)r0 * HID + j];
                    float ih = g_ih[(size_t)r0 * LVL + lv];
                    float fh = g_fh[(size_t)r0 * LVL + lv];
                    float w  = ih * fh;
                    float cn = w * (fv * cp + iv * gv) + (fh - w) * cp + (ih - w) * gv;
                    outC[(size_t)r0 * HID + j] = cn;
                    outH[(size_t)r0 * HID + j] = ov * tanhf(cn);
                }
                {
                    int r1 = r0 + 8;
                    float iv = sigmoidf_(acc[mi][ni][2]);
                    float fv = sigmoidf_(acc[mi][ni][3]);
                    float ov = sigmoidf_(p2);
                    float gv = tanhf(p3);
                    float cp = c_prev[(size_t)r1 * HID + j];
                    float ih = g_ih[(size_t)r1 * LVL + lv];
                    float fh = g_fh[(size_t)r1 * LVL + lv];
                    float w  = ih * fh;
                    float cn = w * (fv * cp + iv * gv) + (fh - w) * cp + (ih - w) * gv;
                    outC[(size_t)r1 * HID + j] = cn;
                    outH[(size_t)r1 * HID + j] = ov * tanhf(cn);
                }
            }
        }
    }
}

// ================= level GEMM: 128x128 tile, split-K over 4 slices (unchanged) =================
#define BK 32
#define LDS 40
__global__ __launch_bounds__(256, 2) void gemm_level(void) {
    __shared__ __half As[2][BM * LDS];
    __shared__ __half Bs[2][BM * LDS];
    const int tid   = threadIdx.x;
    const int lane  = tid & 31;
    const int wid   = tid >> 5;
    const int warpM = wid >> 2;
    const int warpN = wid & 3;
    const int bm    = blockIdx.y;
    const int ks_id = blockIdx.x;             // K split 0..3
    const int kbase = ks_id * (KDIM / KSPLIT);

    const __half* Ag = g_A + (size_t)(bm * BM) * KDIM + kbase;
    const __half* Bg = g_W + (size_t)NGATE * KDIM + kbase;

    float acc[4][4][4];
#pragma unroll
    for (int a = 0; a < 4; a++)
#pragma unroll
        for (int b = 0; b < 4; b++)
#pragma unroll
            for (int c = 0; c < 4; c++) acc[a][b][c] = 0.0f;

    const int KT = (KDIM / KSPLIT) / BK;  // 16

    auto load_tile = [&](int buf, int kt) {
        int k0 = kt * BK;
#pragma unroll
        for (int i = 0; i < 2; i++) {
            int lin = tid + i * 256;
            int row = lin >> 2, ch = lin & 3;
            uint32_t da = smem_u32(&As[buf][row * LDS + ch * 8]);
            const __half* sa = Ag + (size_t)row * KDIM + k0 + ch * 8;
            asm volatile("cp.async.cg.shared.global [%0], [%1], 16;\n" ::"r"(da), "l"(sa));
            uint32_t db = smem_u32(&Bs[buf][row * LDS + ch * 8]);
            const __half* sb = Bg + (size_t)row * KDIM + k0 + ch * 8;
            asm volatile("cp.async.cg.shared.global [%0], [%1], 16;\n" ::"r"(db), "l"(sb));
        }
        asm volatile("cp.async.commit_group;\n");
    };

    load_tile(0, 0);
#pragma unroll 1
    for (int kt = 0; kt < KT; ++kt) {
        int buf = kt & 1;
        if (kt + 1 < KT) {
            load_tile(buf ^ 1, kt + 1);
            asm volatile("cp.async.wait_group 1;\n");
        } else {
            asm volatile("cp.async.wait_group 0;\n");
        }
        __syncthreads();
#pragma unroll
        for (int ks = 0; ks < 2; ++ks) {
            uint32_t afr[4][4];
#pragma unroll
            for (int mi = 0; mi < 4; ++mi) {
                int r  = warpM * 64 + mi * 16 + (lane & 15);
                int ch = ks * 2 + (lane >> 4);
                uint32_t addr = smem_u32(&As[buf][r * LDS + ch * 8]);
                asm volatile("ldmatrix.sync.aligned.m8n8.x4.shared.b16 {%0,%1,%2,%3}, [%4];"
                             : "=r"(afr[mi][0]), "=r"(afr[mi][1]), "=r"(afr[mi][2]), "=r"(afr[mi][3])
                             : "r"(addr));
            }
            uint32_t bfr[4][2];
#pragma unroll
            for (int np = 0; np < 2; ++np) {
                int r  = warpN * 32 + np * 16 + (lane & 15);
                int ch = ks * 2 + (lane >> 4);
                uint32_t addr = smem_u32(&Bs[buf][r * LDS + ch * 8]);
                uint32_t r0, r1, r2, r3;
                asm volatile("ldmatrix.sync.aligned.m8n8.x4.shared.b16 {%0,%1,%2,%3}, [%4];"
                             : "=r"(r0), "=r"(r1), "=r"(r2), "=r"(r3)
                             : "r"(addr));
                bfr[np * 2][0] = r0; bfr[np * 2 + 1][0] = r1;
                bfr[np * 2][1] = r2; bfr[np * 2 + 1][1] = r3;
            }
#pragma unroll
            for (int mi = 0; mi < 4; ++mi)
#pragma unroll
                for (int ni = 0; ni < 4; ++ni) {
                    asm volatile(
                        "mma.sync.aligned.m16n8k16.row.col.f32.f16.f16.f32 "
                        "{%0,%1,%2,%3}, {%4,%5,%6,%7}, {%8,%9}, {%0,%1,%2,%3};"
                        : "+f"(acc[mi][ni][0]), "+f"(acc[mi][ni][1]),
                          "+f"(acc[mi][ni][2]), "+f"(acc[mi][ni][3])
                        : "r"(afr[mi][0]), "r"(afr[mi][1]), "r"(afr[mi][2]), "r"(afr[mi][3]),
                          "r"(bfr[ni][0]), "r"(bfr[ni][1]));
                }
        }
        __syncthreads();
    }

    float* Ldst = g_lev[ks_id];
    int rbase = bm * BM + warpM * 64;
#pragma unroll
    for (int mi = 0; mi < 4; mi++) {
        int r0 = rbase + mi * 16 + (lane >> 2);
#pragma unroll
        for (int ni = 0; ni < 4; ni++) {
            int c0 = warpN * 32 + ni * 8 + (lane & 3) * 2;
            Ldst[(size_t)r0 * NLEV + c0]           = acc[mi][ni][0];
            Ldst[(size_t)r0 * NLEV + c0 + 1]       = acc[mi][ni][1];
            Ldst[(size_t)(r0 + 8) * NLEV + c0]     = acc[mi][ni][2];
            Ldst[(size_t)(r0 + 8) * NLEV + c0 + 1] = acc[mi][ni][3];
        }
    }
}

// -------- per-row: sum split-K partials, softmax + cumsum over 64 levels --------
__global__ void level_kernel() {
    int row  = blockIdx.x * 8 + (threadIdx.x >> 5);
    int lane = threadIdx.x & 31;
    float xi0 = 0.f, xi1 = 0.f, xf0 = 0.f, xf1 = 0.f;
#pragma unroll
    for (int s = 0; s < KSPLIT; s++) {
        const float* L = g_lev[s] + (size_t)row * NLEV;
        xi0 += L[lane];      xi1 += L[32 + lane];
        xf0 += L[64 + lane]; xf1 += L[96 + lane];
    }

    // ---- i_h = forward inclusive cumsum of softmax(cc_f_h) ----
    float m = fmaxf(xf0, xf1);
#pragma unroll
    for (int o = 16; o; o >>= 1) m = fmaxf(m, __shfl_xor_sync(~0u, m, o));
    float e0 = __expf(xf0 - m), e1 = __expf(xf1 - m);
    float s = e0 + e1;
#pragma unroll
    for (int o = 16; o; o >>= 1) s += __shfl_xor_sync(~0u, s, o);
    float inv = 1.0f / s;
    float s0 = e0;
#pragma unroll
    for (int o = 1; o < 32; o <<= 1) { float v = __shfl_up_sync(~0u, s0, o); if (lane >= o) s0 += v; }
    float tot0 = __shfl_sync(~0u, s0, 31);
    float s1 = e1;
#pragma unroll
    for (int o = 1; o < 32; o <<= 1) { float v = __shfl_up_sync(~0u, s1, o); if (lane >= o) s1 += v; }
    g_ih[(size_t)row * LVL + lane]      = s0 * inv;
    g_ih[(size_t)row * LVL + 32 + lane] = (tot0 + s1) * inv;

    // ---- f_h = reverse inclusive cumsum of softmax(cc_i_h) ----
    float mq = fmaxf(xi0, xi1);
#pragma unroll
    for (int o = 16; o; o >>= 1) mq = fmaxf(mq, __shfl_xor_sync(~0u, mq, o));
    float q0 = __expf(xi0 - mq), q1 = __expf(xi1 - mq);
    float sq = q0 + q1;
#pragma unroll
    for (int o = 16; o; o >>= 1) sq += __shfl_xor_sync(~0u, sq, o);
    float invq = 1.0f / sq;
    float r1 = q1;
#pragma unroll
    for (int o = 1; o < 32; o <<= 1) { float v = __shfl_down_sync(~0u, r1, o); if (lane < 32 - o) r1 += v; }
    float tot1 = __shfl_sync(~0u, r1, 0);
    float r0 = q0;
#pragma unroll
    for (int o = 1; o < 32; o <<= 1) { float v = __shfl_down_sync(~0u, r0, o); if (lane < 32 - o) r0 += v; }
    g_fh[(size_t)row * LVL + lane]      = (r0 + tot1) * invq;
    g_fh[(size_t)row * LVL + 32 + lane] = r1 * invq;
}

extern "C" void kernel_launch(void* const* d_in, const int* in_sizes, int n_in,
                              void* d_out, int out_size) {
    const float* input   = (const float*)d_in[0];
    const float* h_prev  = (const float*)d_in[1];
    const float* c_prev  = (const float*)d_in[2];
    const float* W_lstm  = (const float*)d_in[3];
    const float* W_level = (const float*)d_in[4];
    float* out = (float*)d_out;

    const int smem_main = 3 * MSTG2 * 2;   // 3 stages x (A+B) x 18432 B = 110592 B
    cudaFuncSetAttribute(gemm_main, cudaFuncAttributeMaxDynamicSharedMemorySize, smem_main);

    const int prep_blocks = (A4CNT + W4CNT + 255) / 256;
    prep_all<<<prep_blocks, 256>>>(input, h_prev, W_lstm, W_level);        // launch 0
    gemm_level<<<dim3(KSPLIT, BSZ / 128), 256>>>();                        // launch 1
    level_kernel<<<BSZ / 8, 256>>>();                                      // launch 2
    gemm_main<<<dim3(NGATE / BN, BSZ / BM), 256, smem_main>>>(c_prev, out); // launch 3 (ncu slot)
}